// round 1
// baseline (speedup 1.0000x reference)
#include <cuda_runtime.h>

// ---------------- problem constants ----------------
static constexpr int B_  = 2;
static constexpr int T_  = 1024;
static constexpr int D_  = 1024;
static constexpr int H_  = 16;
static constexpr int HKV_ = 4;
static constexpr int HD_ = 64;
static constexpr int HG_ = 8;
static constexpr int DK_ = 64;
static constexpr int DV_ = 128;

// ---------------- scratch (static device arrays; no allocation) ----------------
__device__ float g_qp[B_*T_*D_];          // raw q projection (b,t, h*64+d)
__device__ float g_kp[B_*T_*HKV_*HD_];    // raw k projection
__device__ float g_vp[B_*T_*HKV_*HD_];    // raw v projection
__device__ float g_q [B_*H_*T_*HD_];      // normed+roped q, (b,h,t,d)
__device__ float g_k [B_*HKV_*T_*HD_];    // normed+roped k, (b,h,t,d)
__device__ float g_v [B_*HKV_*T_*HD_];    // v transposed,   (b,h,t,d)
__device__ float g_y [B_*T_*D_];          // attention output (b,t, h*64+d)
__device__ float g_qn[B_*T_*HG_*DK_];     // l2-normed gq
__device__ float g_kn[B_*T_*HG_*DK_];     // l2-normed gk

// ---------------- GEMM: C[M,N] = A[M,K] @ B[N,K]^T  (both K-contiguous) ----------------
__global__ void __launch_bounds__(256, 2) gemm_abt(
    const float* __restrict__ A, const float* __restrict__ Bm,
    float* __restrict__ C, int M, int N, int K)
{
    __shared__ float As[16][128+4];
    __shared__ float Bs[16][64+4];
    const int m0 = blockIdx.y * 128;
    const int n0 = blockIdx.x * 64;
    const int tid = threadIdx.x;
    const int tx = tid & 15, ty = tid >> 4;

    float acc[8][4];
#pragma unroll
    for (int i = 0; i < 8; i++)
#pragma unroll
        for (int j = 0; j < 4; j++) acc[i][j] = 0.f;

    for (int kt = 0; kt < K; kt += 16) {
#pragma unroll
        for (int i = 0; i < 2; i++) {
            int f = tid + i*256;                 // 512 float4 cover 128 rows x 16k
            int row = f >> 2, c4 = f & 3;
            float4 a4 = *(const float4*)(A + (size_t)(m0+row)*K + kt + c4*4);
            As[c4*4+0][row] = a4.x;
            As[c4*4+1][row] = a4.y;
            As[c4*4+2][row] = a4.z;
            As[c4*4+3][row] = a4.w;
        }
        {
            int row = tid >> 2, c4 = tid & 3;    // 256 float4 cover 64 rows x 16k
            float4 b4 = *(const float4*)(Bm + (size_t)(n0+row)*K + kt + c4*4);
            Bs[c4*4+0][row] = b4.x;
            Bs[c4*4+1][row] = b4.y;
            Bs[c4*4+2][row] = b4.z;
            Bs[c4*4+3][row] = b4.w;
        }
        __syncthreads();
#pragma unroll
        for (int kk = 0; kk < 16; kk++) {
            float a[8], bf[4];
            float4 a0 = *(const float4*)&As[kk][ty*8];
            float4 a1 = *(const float4*)&As[kk][ty*8+4];
            a[0]=a0.x; a[1]=a0.y; a[2]=a0.z; a[3]=a0.w;
            a[4]=a1.x; a[5]=a1.y; a[6]=a1.z; a[7]=a1.w;
            float4 b0 = *(const float4*)&Bs[kk][tx*4];
            bf[0]=b0.x; bf[1]=b0.y; bf[2]=b0.z; bf[3]=b0.w;
#pragma unroll
            for (int i = 0; i < 8; i++)
#pragma unroll
                for (int j = 0; j < 4; j++)
                    acc[i][j] = fmaf(a[i], bf[j], acc[i][j]);
        }
        __syncthreads();
    }
#pragma unroll
    for (int i = 0; i < 8; i++) {
        float4 o = make_float4(acc[i][0], acc[i][1], acc[i][2], acc[i][3]);
        *(float4*)(C + (size_t)(m0 + ty*8 + i)*N + n0 + tx*4) = o;
    }
}

// ---------------- RMSNorm + RoPE (+gain), transpose to (b,h,t,d) ----------------
// one warp per (b,t,head); lane owns dims (lane, lane+32)
__global__ void rmsnorm_rope(const float* __restrict__ src, float* __restrict__ dst,
                             const float* __restrict__ gain, int nheads)
{
    int warp = threadIdx.x >> 5, lane = threadIdx.x & 31;
    int item = blockIdx.x*4 + warp;              // (b*T + t)*nheads + h
    int h = item % nheads;
    int tpos = (item / nheads) & (T_-1);
    int b = item / (nheads*T_);
    const float* p = src + (size_t)item*64;
    float x1 = p[lane], x2 = p[lane+32];
    float ss = x1*x1 + x2*x2;
#pragma unroll
    for (int o = 16; o > 0; o >>= 1) ss += __shfl_xor_sync(0xffffffffu, ss, o);
    float r = rsqrtf(ss*(1.0f/64.0f) + 1e-6f);
    x1 *= r; x2 *= r;
    // inv_freq = 10000^(-lane/32)
    float invf = expf(-(float)lane * (9.210340371976184f/32.0f));
    float ang = (float)tpos * invf;
    float sv, cv;
    sincosf(ang, &sv, &cv);
    float o1 = x1*cv + x2*sv;
    float o2 = x2*cv - x1*sv;
    float g = gain ? gain[h] : 1.0f;
    float* q = dst + (((size_t)(b*nheads + h)*T_) + tpos)*64;
    q[lane]    = o1*g;
    q[lane+32] = o2*g;
}

// ---------------- V transpose (b,t,h,d) -> (b,h,t,d) ----------------
__global__ void transpose_v_kernel()
{
    int idx = blockIdx.x*256 + threadIdx.x;
    int d = idx & 63;
    int h = (idx >> 6) & 3;
    int t = (idx >> 8) & 1023;
    int b = idx >> 18;
    g_v[(((size_t)(b*HKV_ + h))*T_ + t)*64 + d] = g_vp[idx];
}

// ---------------- L2 norm over 64-dim vectors (for gq/gk) ----------------
__global__ void l2norm64(const float* __restrict__ src, float* __restrict__ dst)
{
    int warp = threadIdx.x >> 5, lane = threadIdx.x & 31;
    int item = blockIdx.x*4 + warp;
    const float* p = src + (size_t)item*64;
    float x1 = p[lane], x2 = p[lane+32];
    float ss = x1*x1 + x2*x2;
#pragma unroll
    for (int o = 16; o > 0; o >>= 1) ss += __shfl_xor_sync(0xffffffffu, ss, o);
    float n = sqrtf(ss);
    float r = 1.0f / fmaxf(n, 1e-6f);
    dst[(size_t)item*64 + lane]      = x1*r;
    dst[(size_t)item*64 + lane + 32] = x2*r;
}

// ---------------- causal flash attention ----------------
// grid (T/128, H, B), 128 threads; each thread owns one query row.
__global__ void __launch_bounds__(128, 1) attn_kernel()
{
    const int b = blockIdx.z, h = blockIdx.y;
    const int qi = blockIdx.x*128 + threadIdx.x;
    __shared__ float Ks[32][64];
    __shared__ float Vs[32][64];
    const float* qp = g_q + (((size_t)(b*H_ + h)*T_) + qi)*64;
    const float* kb = g_k + ((size_t)(b*HKV_ + (h>>2))*T_)*64;
    const float* vb = g_v + ((size_t)(b*HKV_ + (h>>2))*T_)*64;

    float q[64];
#pragma unroll
    for (int c = 0; c < 16; c++) {
        float4 v4 = ((const float4*)qp)[c];
        q[c*4+0]=v4.x; q[c*4+1]=v4.y; q[c*4+2]=v4.z; q[c*4+3]=v4.w;
    }
    float acc[64];
#pragma unroll
    for (int c = 0; c < 64; c++) acc[c] = 0.f;
    float m = -1e30f, l = 0.f;

    const int ntiles = (blockIdx.x + 1) * 4;     // keys 0 .. blockIdx.x*128+127
    for (int tile = 0; tile < ntiles; ++tile) {
        __syncthreads();
#pragma unroll
        for (int i = 0; i < 4; i++) {            // 512 float4 per array / 128 thr
            int f = threadIdx.x + i*128;
            int row = f >> 4, c4 = f & 15;
            const float4* kg = (const float4*)(kb + (size_t)(tile*32 + row)*64);
            const float4* vg = (const float4*)(vb + (size_t)(tile*32 + row)*64);
            *(float4*)&Ks[row][c4*4] = kg[c4];
            *(float4*)&Vs[row][c4*4] = vg[c4];
        }
        __syncthreads();

        float s[32];
        float mt = -1e30f;
#pragma unroll
        for (int j = 0; j < 32; j++) {
            float d0=0.f,d1=0.f,d2=0.f,d3=0.f;
            const float4* kr = (const float4*)&Ks[j][0];
#pragma unroll
            for (int c = 0; c < 16; c++) {
                float4 kv = kr[c];
                d0 = fmaf(q[c*4+0], kv.x, d0);
                d1 = fmaf(q[c*4+1], kv.y, d1);
                d2 = fmaf(q[c*4+2], kv.z, d2);
                d3 = fmaf(q[c*4+3], kv.w, d3);
            }
            float sc = ((d0+d1)+(d2+d3)) * 0.125f;
            int kj = tile*32 + j;
            s[j] = (kj <= qi) ? sc : -1e30f;
            mt = fmaxf(mt, s[j]);
        }
        float mnew = fmaxf(m, mt);
        float corr = __expf(m - mnew);
        m = mnew;
        l *= corr;
#pragma unroll
        for (int c = 0; c < 64; c++) acc[c] *= corr;
#pragma unroll
        for (int j = 0; j < 32; j++) {
            float p = __expf(s[j] - mnew);
            l += p;
            const float4* vr = (const float4*)&Vs[j][0];
#pragma unroll
            for (int c = 0; c < 16; c++) {
                float4 vv = vr[c];
                acc[c*4+0] = fmaf(p, vv.x, acc[c*4+0]);
                acc[c*4+1] = fmaf(p, vv.y, acc[c*4+1]);
                acc[c*4+2] = fmaf(p, vv.z, acc[c*4+2]);
                acc[c*4+3] = fmaf(p, vv.w, acc[c*4+3]);
            }
        }
    }
    float inv = 1.f / l;
    float* op = g_y + ((size_t)(b*T_ + qi)*D_) + h*64;
#pragma unroll
    for (int c = 0; c < 16; c++) {
        float4 o = make_float4(acc[c*4+0]*inv, acc[c*4+1]*inv,
                               acc[c*4+2]*inv, acc[c*4+3]*inv);
        ((float4*)op)[c] = o;
    }
}

// ---------------- gated delta net scan (adds into out) ----------------
// Columns v are independent: one lane-pair per column (half = d-range split),
// 32 columns per block, 4 blocks per (b,h) -> grid (B*HG, 4), 64 threads.
__global__ void __launch_bounds__(64) gdn_kernel(const float* __restrict__ gv,
    const float* __restrict__ alpha, const float* __restrict__ beta,
    float* __restrict__ out)
{
    const int b = blockIdx.x >> 3;
    const int h = blockIdx.x & 7;
    const int tid = threadIdx.x;
    const int v = blockIdx.y*32 + (tid >> 1);
    const int half = tid & 1;                    // d in [half*32, half*32+32)
    __shared__ float ks[64], qs[64];
    float S[32];
#pragma unroll
    for (int i = 0; i < 32; i++) S[i] = 0.f;

    const float* kptr = g_kn + ((size_t)b*T_*HG_ + h)*64 + tid;
    const float* qptr = g_qn + ((size_t)b*T_*HG_ + h)*64 + tid;
    const float* vptr = gv   + ((size_t)b*T_*HG_ + h)*128 + v;
    const float* aptr = alpha + (size_t)b*T_*HG_ + h;
    const float* bptr = beta  + (size_t)b*T_*HG_ + h;
    float* optr = out + (size_t)b*T_*D_ + h*DV_ + v;

    float pk = *kptr, pq = *qptr, pv = *vptr, pa = *aptr, pb = *bptr;

    for (int t = 0; t < T_; ++t) {
        __syncthreads();                          // shared free from prev step
        ks[tid] = pk; qs[tid] = pq;
        float a = pa, bb = pb, vt = pv;
        __syncthreads();
        if (t < T_-1) {                           // prefetch next step
            kptr += HG_*64; qptr += HG_*64; vptr += HG_*128; aptr += HG_; bptr += HG_;
            pk = *kptr; pq = *qptr; pv = *vptr; pa = *aptr; pb = *bptr;
        }
        float kr[32];
#pragma unroll
        for (int c = 0; c < 8; c++) {
            float4 k4 = *(const float4*)&ks[half*32 + c*4];
            kr[c*4+0]=k4.x; kr[c*4+1]=k4.y; kr[c*4+2]=k4.z; kr[c*4+3]=k4.w;
        }
        float r0=0.f,r1=0.f,r2=0.f,r3=0.f;
#pragma unroll
        for (int c = 0; c < 8; c++) {
            r0 = fmaf(kr[c*4+0], S[c*4+0], r0);
            r1 = fmaf(kr[c*4+1], S[c*4+1], r1);
            r2 = fmaf(kr[c*4+2], S[c*4+2], r2);
            r3 = fmaf(kr[c*4+3], S[c*4+3], r3);
        }
        float kS = (r0+r1)+(r2+r3);
        kS += __shfl_xor_sync(0xffffffffu, kS, 1);           // full 64-d dot
        float coef = fmaf(-a*bb, kS, vt);                    // v - a*b*kS
#pragma unroll
        for (int i = 0; i < 32; i++) S[i] = fmaf(coef, kr[i], a*S[i]);
        float o0=0.f,o1=0.f,o2=0.f,o3=0.f;
#pragma unroll
        for (int c = 0; c < 8; c++) {
            float4 q4 = *(const float4*)&qs[half*32 + c*4];
            o0 = fmaf(S[c*4+0], q4.x, o0);
            o1 = fmaf(S[c*4+1], q4.y, o1);
            o2 = fmaf(S[c*4+2], q4.z, o2);
            o3 = fmaf(S[c*4+3], q4.w, o3);
        }
        float o = (o0+o1)+(o2+o3);
        o += __shfl_xor_sync(0xffffffffu, o, 1);
        if (half == 0) *optr += o;                // out already holds y_attn
        optr += D_;
    }
}

// ---------------- launch ----------------
extern "C" void kernel_launch(void* const* d_in, const int* in_sizes, int n_in,
                              void* d_out, int out_size)
{
    const float* x     = (const float*)d_in[0];
    const float* Wq    = (const float*)d_in[1];
    const float* Wk    = (const float*)d_in[2];
    const float* Wv    = (const float*)d_in[3];
    const float* Wo    = (const float*)d_in[4];
    const float* qg    = (const float*)d_in[5];
    const float* gq    = (const float*)d_in[6];
    const float* gk    = (const float*)d_in[7];
    const float* gv    = (const float*)d_in[8];
    const float* alpha = (const float*)d_in[9];
    const float* beta  = (const float*)d_in[10];
    float* out = (float*)d_out;

    float *qp,*kp,*vp,*qh,*kh,*yb,*qn,*kn;
    cudaGetSymbolAddress((void**)&qp, g_qp);
    cudaGetSymbolAddress((void**)&kp, g_kp);
    cudaGetSymbolAddress((void**)&vp, g_vp);
    cudaGetSymbolAddress((void**)&qh, g_q);
    cudaGetSymbolAddress((void**)&kh, g_k);
    cudaGetSymbolAddress((void**)&yb, g_y);
    cudaGetSymbolAddress((void**)&qn, g_qn);
    cudaGetSymbolAddress((void**)&kn, g_kn);

    // projections: C = x @ W^T
    gemm_abt<<<dim3(D_/64, (B_*T_)/128), 256>>>(x, Wq, qp, B_*T_, D_, D_);
    gemm_abt<<<dim3((HKV_*HD_)/64, (B_*T_)/128), 256>>>(x, Wk, kp, B_*T_, HKV_*HD_, D_);
    gemm_abt<<<dim3((HKV_*HD_)/64, (B_*T_)/128), 256>>>(x, Wv, vp, B_*T_, HKV_*HD_, D_);

    // per-head RMSNorm + RoPE (+gain for q), layout to (b,h,t,d)
    rmsnorm_rope<<<(B_*T_*H_)/4, 128>>>(qp, qh, qg, H_);
    rmsnorm_rope<<<(B_*T_*HKV_)/4, 128>>>(kp, kh, (const float*)nullptr, HKV_);
    transpose_v_kernel<<<(B_*T_*HKV_*HD_)/256, 256>>>();

    // GDN input normalization
    l2norm64<<<(B_*T_*HG_)/4, 128>>>(gq, qn);
    l2norm64<<<(B_*T_*HG_)/4, 128>>>(gk, kn);

    // causal attention -> g_y (b,t,h*64+d)
    attn_kernel<<<dim3(T_/128, H_, B_), 128>>>();

    // output projection writes y_attn into d_out
    gemm_abt<<<dim3(D_/64, (B_*T_)/128), 256>>>(yb, Wo, out, B_*T_, D_, D_);

    // GDN scan accumulates y_gdn into d_out
    gdn_kernel<<<dim3(B_*HG_, DV_/32), 64>>>(gv, alpha, beta, out);
}

// round 3
// speedup vs baseline: 1.1045x; 1.1045x over previous
#include <cuda_runtime.h>
#include <cuda_bf16.h>
#include <cstdint>

// ---------------- problem constants ----------------
static constexpr int B_  = 2;
static constexpr int T_  = 1024;
static constexpr int D_  = 1024;
static constexpr int H_  = 16;
static constexpr int HKV_ = 4;
static constexpr int HD_ = 64;
static constexpr int HG_ = 8;
static constexpr int DV_ = 128;

static constexpr int MT_ = B_*T_;     // 2048 rows

// ---------------- scratch (static device arrays; no allocation) ----------------
__device__ float g_qp[B_*T_*D_];
__device__ float g_kp[B_*T_*HKV_*HD_];
__device__ float g_vp[B_*T_*HKV_*HD_];
__device__ float g_q [B_*H_*T_*HD_];
__device__ float g_k [B_*HKV_*T_*HD_];
__device__ float g_v [B_*HKV_*T_*HD_];
__device__ float g_y [B_*T_*D_];
__device__ float g_qn[B_*T_*HG_*64];
__device__ float g_kn[B_*T_*HG_*64];

// bf16 split-precision planes
__device__ __nv_bfloat16 g_xh[MT_*D_],  g_xl[MT_*D_];
__device__ __nv_bfloat16 g_wqh[D_*D_],  g_wql[D_*D_];
__device__ __nv_bfloat16 g_wkh[HKV_*HD_*D_], g_wkl[HKV_*HD_*D_];
__device__ __nv_bfloat16 g_wvh[HKV_*HD_*D_], g_wvl[HKV_*HD_*D_];
__device__ __nv_bfloat16 g_woh[D_*D_],  g_wol[D_*D_];
__device__ __nv_bfloat16 g_yh[MT_*D_],  g_yl[MT_*D_];

// ---------------- small PTX helpers (baseline ISA only) ----------------
__device__ __forceinline__ uint32_t smem_u32(const void* p) {
    uint32_t a;
    asm("{ .reg .u64 t; cvta.to.shared.u64 t, %1; cvt.u32.u64 %0, t; }" : "=r"(a) : "l"(p));
    return a;
}
__device__ __forceinline__ void ldsm4(uint32_t (&r)[4], uint32_t addr) {
    asm volatile("ldmatrix.sync.aligned.m8n8.x4.shared.b16 {%0,%1,%2,%3}, [%4];"
        : "=r"(r[0]), "=r"(r[1]), "=r"(r[2]), "=r"(r[3]) : "r"(addr));
}
__device__ __forceinline__ void mma16816(float (&d)[4], const uint32_t (&a)[4],
                                         const uint32_t* b) {
    asm volatile("mma.sync.aligned.m16n8k16.row.col.f32.bf16.bf16.f32 "
        "{%0,%1,%2,%3}, {%4,%5,%6,%7}, {%8,%9}, {%0,%1,%2,%3};"
        : "+f"(d[0]), "+f"(d[1]), "+f"(d[2]), "+f"(d[3])
        : "r"(a[0]), "r"(a[1]), "r"(a[2]), "r"(a[3]), "r"(b[0]), "r"(b[1]));
}
__device__ __forceinline__ void cp16(uint32_t saddr, const void* gaddr) {
    asm volatile("cp.async.cg.shared.global [%0], [%1], 16;" :: "r"(saddr), "l"(gaddr));
}
#define CP_COMMIT() asm volatile("cp.async.commit_group;" ::: "memory")
#define CP_WAIT(n)  asm volatile("cp.async.wait_group %0;" :: "n"(n) : "memory")

// ---------------- fp32 -> bf16 hi/lo split ----------------
__global__ void split_bf16(const float* __restrict__ src,
                           __nv_bfloat16* __restrict__ hi,
                           __nv_bfloat16* __restrict__ lo, int n4)
{
    int i = blockIdx.x * 256 + threadIdx.x;
    if (i >= n4) return;
    float4 v = ((const float4*)src)[i];
    __nv_bfloat16 h0 = __float2bfloat16(v.x), h1 = __float2bfloat16(v.y);
    __nv_bfloat16 h2 = __float2bfloat16(v.z), h3 = __float2bfloat16(v.w);
    __nv_bfloat16 l0 = __float2bfloat16(v.x - __bfloat162float(h0));
    __nv_bfloat16 l1 = __float2bfloat16(v.y - __bfloat162float(h1));
    __nv_bfloat16 l2 = __float2bfloat16(v.z - __bfloat162float(h2));
    __nv_bfloat16 l3 = __float2bfloat16(v.w - __bfloat162float(h3));
    ((__nv_bfloat162*)hi)[2*i]   = __nv_bfloat162(h0, h1);
    ((__nv_bfloat162*)hi)[2*i+1] = __nv_bfloat162(h2, h3);
    ((__nv_bfloat162*)lo)[2*i]   = __nv_bfloat162(l0, l1);
    ((__nv_bfloat162*)lo)[2*i+1] = __nv_bfloat162(l2, l3);
}

// ---------------- mma.sync bf16x2-split GEMM ----------------
// C[M,N] = A[M,K] @ B[N,K]^T, near-fp32. CTA tile 128x128, K-chunk 32.
// smem: 2 stages x 4 planes (Ah, Al, Bh, Bl), each 128 rows x 32 bf16,
// row stride 40 bf16 (80 B = 5*16B, odd -> conflict-free ldmatrix).
static constexpr int ROWSTRIDE = 40;                 // bf16 elems
static constexpr int PLANE_B = 128 * ROWSTRIDE * 2;  // 10240 B
static constexpr int STAGE_B = 4 * PLANE_B;          // 40960 B
static constexpr int GEMM_SMEM = 2 * STAGE_B;        // 81920 B

__global__ void __launch_bounds__(512) gemm_mma(
    const __nv_bfloat16* __restrict__ Ah, const __nv_bfloat16* __restrict__ Al,
    const __nv_bfloat16* __restrict__ Bh, const __nv_bfloat16* __restrict__ Bl,
    float* __restrict__ C, int M, int N, int K)
{
    extern __shared__ __align__(128) char smem[];
    const uint32_t sb = smem_u32(smem);
    const int tid = threadIdx.x;
    const int wid = tid >> 5, lane = tid & 31;
    const int wr = wid & 3, wc = wid >> 2;           // 4x4 warp grid
    const int m0 = blockIdx.y * 128;
    const int n0 = blockIdx.x * 128;
    const int NC = K >> 5;                           // K chunks of 32

    // cp.async geometry: 512 threads cover 128 rows x 4 x 16B per plane
    const int lrow = tid >> 2, lc16 = tid & 3;
    const uint32_t soff = (uint32_t)(lrow * (ROWSTRIDE*2) + lc16 * 16);
    const size_t gaoff = (size_t)(m0 + lrow) * K + lc16 * 8;
    const size_t gboff = (size_t)(n0 + lrow) * K + lc16 * 8;

    auto issue = [&](int kc, int st) {
        uint32_t sd = sb + st * STAGE_B + soff;
        const int ko = kc * 32;
        cp16(sd + 0*PLANE_B, Ah + gaoff + ko);
        cp16(sd + 1*PLANE_B, Al + gaoff + ko);
        cp16(sd + 2*PLANE_B, Bh + gboff + ko);
        cp16(sd + 3*PLANE_B, Bl + gboff + ko);
        CP_COMMIT();
    };

    float acc[2][4][4];
#pragma unroll
    for (int mt = 0; mt < 2; mt++)
#pragma unroll
        for (int nt = 0; nt < 4; nt++)
#pragma unroll
            for (int j = 0; j < 4; j++) acc[mt][nt][j] = 0.f;

    issue(0, 0);
    if (NC > 1) issue(1, 1);

    const int lr = lane & 15, lchi = lane >> 4;      // ldmatrix lane geometry

    for (int c = 0; c < NC; c++) {
        if (c + 1 < NC) { CP_WAIT(1); } else { CP_WAIT(0); }
        __syncthreads();
        const uint32_t st = sb + (c & 1) * STAGE_B;
#pragma unroll
        for (int ks = 0; ks < 2; ks++) {
            const int koff = ks * 16 + lchi * 8;
            uint32_t aH[2][4], aL[2][4], bH[4][2], bL[4][2];
#pragma unroll
            for (int mt = 0; mt < 2; mt++) {
                uint32_t ro = (uint32_t)(((wr*32 + mt*16 + lr) * ROWSTRIDE + koff) * 2);
                ldsm4(aH[mt], st + 0*PLANE_B + ro);
                ldsm4(aL[mt], st + 1*PLANE_B + ro);
            }
#pragma unroll
            for (int np = 0; np < 2; np++) {
                uint32_t ro = (uint32_t)(((wc*32 + np*16 + lr) * ROWSTRIDE + koff) * 2);
                uint32_t t[4];
                ldsm4(t, st + 2*PLANE_B + ro);
                bH[np*2+0][0] = t[0]; bH[np*2+0][1] = t[2];
                bH[np*2+1][0] = t[1]; bH[np*2+1][1] = t[3];
                ldsm4(t, st + 3*PLANE_B + ro);
                bL[np*2+0][0] = t[0]; bL[np*2+0][1] = t[2];
                bL[np*2+1][0] = t[1]; bL[np*2+1][1] = t[3];
            }
#pragma unroll
            for (int mt = 0; mt < 2; mt++)
#pragma unroll
                for (int nt = 0; nt < 4; nt++) {
                    mma16816(acc[mt][nt], aH[mt], bH[nt]);
                    mma16816(acc[mt][nt], aH[mt], bL[nt]);
                    mma16816(acc[mt][nt], aL[mt], bH[nt]);
                }
        }
        __syncthreads();
        if (c + 2 < NC) issue(c + 2, c & 1);
    }

    // epilogue
    const int er = m0 + wr*32 + (lane >> 2);
    const int ec = n0 + wc*32 + (lane & 3) * 2;
#pragma unroll
    for (int mt = 0; mt < 2; mt++)
#pragma unroll
        for (int nt = 0; nt < 4; nt++) {
            float* p0 = C + (size_t)(er + mt*16) * N + ec + nt*8;
            float* p1 = C + (size_t)(er + mt*16 + 8) * N + ec + nt*8;
            *(float2*)p0 = make_float2(acc[mt][nt][0], acc[mt][nt][1]);
            *(float2*)p1 = make_float2(acc[mt][nt][2], acc[mt][nt][3]);
        }
}

// ---------------- RMSNorm + RoPE (+gain), transpose to (b,h,t,d) ----------------
__global__ void rmsnorm_rope(const float* __restrict__ src, float* __restrict__ dst,
                             const float* __restrict__ gain, int nheads)
{
    int warp = threadIdx.x >> 5, lane = threadIdx.x & 31;
    int item = blockIdx.x*4 + warp;
    int h = item % nheads;
    int tpos = (item / nheads) & (T_-1);
    int b = item / (nheads*T_);
    const float* p = src + (size_t)item*64;
    float x1 = p[lane], x2 = p[lane+32];
    float ss = x1*x1 + x2*x2;
#pragma unroll
    for (int o = 16; o > 0; o >>= 1) ss += __shfl_xor_sync(0xffffffffu, ss, o);
    float r = rsqrtf(ss*(1.0f/64.0f) + 1e-6f);
    x1 *= r; x2 *= r;
    float invf = expf(-(float)lane * (9.210340371976184f/32.0f));
    float ang = (float)tpos * invf;
    float sv, cv;
    sincosf(ang, &sv, &cv);
    float o1 = x1*cv + x2*sv;
    float o2 = x2*cv - x1*sv;
    float g = gain ? gain[h] : 1.0f;
    float* q = dst + (((size_t)(b*nheads + h)*T_) + tpos)*64;
    q[lane]    = o1*g;
    q[lane+32] = o2*g;
}

__global__ void transpose_v_kernel()
{
    int idx = blockIdx.x*256 + threadIdx.x;
    int d = idx & 63;
    int h = (idx >> 6) & 3;
    int t = (idx >> 8) & 1023;
    int b = idx >> 18;
    g_v[(((size_t)(b*HKV_ + h))*T_ + t)*64 + d] = g_vp[idx];
}

__global__ void l2norm64(const float* __restrict__ src, float* __restrict__ dst)
{
    int warp = threadIdx.x >> 5, lane = threadIdx.x & 31;
    int item = blockIdx.x*4 + warp;
    const float* p = src + (size_t)item*64;
    float x1 = p[lane], x2 = p[lane+32];
    float ss = x1*x1 + x2*x2;
#pragma unroll
    for (int o = 16; o > 0; o >>= 1) ss += __shfl_xor_sync(0xffffffffu, ss, o);
    float n = sqrtf(ss);
    float r = 1.0f / fmaxf(n, 1e-6f);
    dst[(size_t)item*64 + lane]      = x1*r;
    dst[(size_t)item*64 + lane + 32] = x2*r;
}

// ---------------- causal flash attention (heavy blocks first) ----------------
__global__ void __launch_bounds__(128, 1) attn_kernel()
{
    const int qt = 7 - (blockIdx.x >> 5);        // heaviest query tiles first
    const int hb = blockIdx.x & 31;
    const int h = hb & 15, b = hb >> 4;
    const int qi = qt*128 + threadIdx.x;
    __shared__ float Ks[32][64];
    __shared__ float Vs[32][64];
    const float* qp = g_q + (((size_t)(b*H_ + h)*T_) + qi)*64;
    const float* kb = g_k + ((size_t)(b*HKV_ + (h>>2))*T_)*64;
    const float* vb = g_v + ((size_t)(b*HKV_ + (h>>2))*T_)*64;

    float q[64];
#pragma unroll
    for (int c = 0; c < 16; c++) {
        float4 v4 = ((const float4*)qp)[c];
        q[c*4+0]=v4.x; q[c*4+1]=v4.y; q[c*4+2]=v4.z; q[c*4+3]=v4.w;
    }
    float acc[64];
#pragma unroll
    for (int c = 0; c < 64; c++) acc[c] = 0.f;
    float m = -1e30f, l = 0.f;

    const int ntiles = (qt + 1) * 4;
    for (int tile = 0; tile < ntiles; ++tile) {
        __syncthreads();
#pragma unroll
        for (int i = 0; i < 4; i++) {
            int f = threadIdx.x + i*128;
            int row = f >> 4, c4 = f & 15;
            const float4* kg = (const float4*)(kb + (size_t)(tile*32 + row)*64);
            const float4* vg = (const float4*)(vb + (size_t)(tile*32 + row)*64);
            *(float4*)&Ks[row][c4*4] = kg[c4];
            *(float4*)&Vs[row][c4*4] = vg[c4];
        }
        __syncthreads();

        float s[32];
        float mt = -1e30f;
#pragma unroll
        for (int j = 0; j < 32; j++) {
            float d0=0.f,d1=0.f,d2=0.f,d3=0.f;
            const float4* kr = (const float4*)&Ks[j][0];
#pragma unroll
            for (int c = 0; c < 16; c++) {
                float4 kv = kr[c];
                d0 = fmaf(q[c*4+0], kv.x, d0);
                d1 = fmaf(q[c*4+1], kv.y, d1);
                d2 = fmaf(q[c*4+2], kv.z, d2);
                d3 = fmaf(q[c*4+3], kv.w, d3);
            }
            float sc = ((d0+d1)+(d2+d3)) * 0.125f;
            int kj = tile*32 + j;
            s[j] = (kj <= qi) ? sc : -1e30f;
            mt = fmaxf(mt, s[j]);
        }
        float mnew = fmaxf(m, mt);
        float corr = __expf(m - mnew);
        m = mnew;
        l *= corr;
#pragma unroll
        for (int c = 0; c < 64; c++) acc[c] *= corr;
#pragma unroll
        for (int j = 0; j < 32; j++) {
            float p = __expf(s[j] - mnew);
            l += p;
            const float4* vr = (const float4*)&Vs[j][0];
#pragma unroll
            for (int c = 0; c < 16; c++) {
                float4 vv = vr[c];
                acc[c*4+0] = fmaf(p, vv.x, acc[c*4+0]);
                acc[c*4+1] = fmaf(p, vv.y, acc[c*4+1]);
                acc[c*4+2] = fmaf(p, vv.z, acc[c*4+2]);
                acc[c*4+3] = fmaf(p, vv.w, acc[c*4+3]);
            }
        }
    }
    float inv = 1.f / l;
    float* op = g_y + ((size_t)(b*T_ + qi)*D_) + h*64;
#pragma unroll
    for (int c = 0; c < 16; c++) {
        float4 o = make_float4(acc[c*4+0]*inv, acc[c*4+1]*inv,
                               acc[c*4+2]*inv, acc[c*4+3]*inv);
        ((float4*)op)[c] = o;
    }
}

// ---------------- gated delta net scan (adds into out) ----------------
__global__ void __launch_bounds__(64) gdn_kernel(const float* __restrict__ gv,
    const float* __restrict__ alpha, const float* __restrict__ beta,
    float* __restrict__ out)
{
    const int b = blockIdx.x >> 3;
    const int h = blockIdx.x & 7;
    const int tid = threadIdx.x;
    const int v = blockIdx.y*32 + (tid >> 1);
    const int half = tid & 1;
    __shared__ float ks[64], qs[64];
    float S[32];
#pragma unroll
    for (int i = 0; i < 32; i++) S[i] = 0.f;

    const float* kptr = g_kn + ((size_t)b*T_*HG_ + h)*64 + tid;
    const float* qptr = g_qn + ((size_t)b*T_*HG_ + h)*64 + tid;
    const float* vptr = gv   + ((size_t)b*T_*HG_ + h)*128 + v;
    const float* aptr = alpha + (size_t)b*T_*HG_ + h;
    const float* bptr = beta  + (size_t)b*T_*HG_ + h;
    float* optr = out + (size_t)b*T_*D_ + h*DV_ + v;

    float pk = *kptr, pq = *qptr, pv = *vptr, pa = *aptr, pb = *bptr;

    for (int t = 0; t < T_; ++t) {
        __syncthreads();
        ks[tid] = pk; qs[tid] = pq;
        float a = pa, bb = pb, vt = pv;
        __syncthreads();
        if (t < T_-1) {
            kptr += HG_*64; qptr += HG_*64; vptr += HG_*128; aptr += HG_; bptr += HG_;
            pk = *kptr; pq = *qptr; pv = *vptr; pa = *aptr; pb = *bptr;
        }
        float kr[32];
#pragma unroll
        for (int c = 0; c < 8; c++) {
            float4 k4 = *(const float4*)&ks[half*32 + c*4];
            kr[c*4+0]=k4.x; kr[c*4+1]=k4.y; kr[c*4+2]=k4.z; kr[c*4+3]=k4.w;
        }
        float r0=0.f,r1=0.f,r2=0.f,r3=0.f;
#pragma unroll
        for (int c = 0; c < 8; c++) {
            r0 = fmaf(kr[c*4+0], S[c*4+0], r0);
            r1 = fmaf(kr[c*4+1], S[c*4+1], r1);
            r2 = fmaf(kr[c*4+2], S[c*4+2], r2);
            r3 = fmaf(kr[c*4+3], S[c*4+3], r3);
        }
        float kS = (r0+r1)+(r2+r3);
        kS += __shfl_xor_sync(0xffffffffu, kS, 1);
        float coef = fmaf(-a*bb, kS, vt);
#pragma unroll
        for (int i = 0; i < 32; i++) S[i] = fmaf(coef, kr[i], a*S[i]);
        float o0=0.f,o1=0.f,o2=0.f,o3=0.f;
#pragma unroll
        for (int c = 0; c < 8; c++) {
            float4 q4 = *(const float4*)&qs[half*32 + c*4];
            o0 = fmaf(S[c*4+0], q4.x, o0);
            o1 = fmaf(S[c*4+1], q4.y, o1);
            o2 = fmaf(S[c*4+2], q4.z, o2);
            o3 = fmaf(S[c*4+3], q4.w, o3);
        }
        float o = (o0+o1)+(o2+o3);
        o += __shfl_xor_sync(0xffffffffu, o, 1);
        if (half == 0) *optr += o;
        optr += D_;
    }
}

// ---------------- launch ----------------
extern "C" void kernel_launch(void* const* d_in, const int* in_sizes, int n_in,
                              void* d_out, int out_size)
{
    const float* x     = (const float*)d_in[0];
    const float* Wq    = (const float*)d_in[1];
    const float* Wk    = (const float*)d_in[2];
    const float* Wv    = (const float*)d_in[3];
    const float* Wo    = (const float*)d_in[4];
    const float* qg    = (const float*)d_in[5];
    const float* gq    = (const float*)d_in[6];
    const float* gk    = (const float*)d_in[7];
    const float* gv    = (const float*)d_in[8];
    const float* alpha = (const float*)d_in[9];
    const float* beta  = (const float*)d_in[10];
    float* out = (float*)d_out;

    float *qp,*kp,*vp,*qh,*kh,*yb,*qn,*kn;
    cudaGetSymbolAddress((void**)&qp, g_qp);
    cudaGetSymbolAddress((void**)&kp, g_kp);
    cudaGetSymbolAddress((void**)&vp, g_vp);
    cudaGetSymbolAddress((void**)&qh, g_q);
    cudaGetSymbolAddress((void**)&kh, g_k);
    cudaGetSymbolAddress((void**)&yb, g_y);
    cudaGetSymbolAddress((void**)&qn, g_qn);
    cudaGetSymbolAddress((void**)&kn, g_kn);

    __nv_bfloat16 *xh,*xl,*wqh,*wql,*wkh,*wkl,*wvh,*wvl,*woh,*wol,*yh,*yl;
    cudaGetSymbolAddress((void**)&xh, g_xh);   cudaGetSymbolAddress((void**)&xl, g_xl);
    cudaGetSymbolAddress((void**)&wqh, g_wqh); cudaGetSymbolAddress((void**)&wql, g_wql);
    cudaGetSymbolAddress((void**)&wkh, g_wkh); cudaGetSymbolAddress((void**)&wkl, g_wkl);
    cudaGetSymbolAddress((void**)&wvh, g_wvh); cudaGetSymbolAddress((void**)&wvl, g_wvl);
    cudaGetSymbolAddress((void**)&woh, g_woh); cudaGetSymbolAddress((void**)&wol, g_wol);
    cudaGetSymbolAddress((void**)&yh, g_yh);   cudaGetSymbolAddress((void**)&yl, g_yl);

    cudaFuncSetAttribute(gemm_mma, cudaFuncAttributeMaxDynamicSharedMemorySize, GEMM_SMEM);

    // split-precision conversions
    split_bf16<<<(MT_*D_/4 + 255)/256, 256>>>(x,  xh,  xl,  MT_*D_/4);
    split_bf16<<<(D_*D_/4 + 255)/256, 256>>>(Wq, wqh, wql, D_*D_/4);
    split_bf16<<<(HKV_*HD_*D_/4 + 255)/256, 256>>>(Wk, wkh, wkl, HKV_*HD_*D_/4);
    split_bf16<<<(HKV_*HD_*D_/4 + 255)/256, 256>>>(Wv, wvh, wvl, HKV_*HD_*D_/4);
    split_bf16<<<(D_*D_/4 + 255)/256, 256>>>(Wo, woh, wol, D_*D_/4);

    // projections on tensor cores (HMMA)
    gemm_mma<<<dim3(D_/128, MT_/128), 512, GEMM_SMEM>>>(xh, xl, wqh, wql, qp, MT_, D_, D_);
    gemm_mma<<<dim3((HKV_*HD_)/128, MT_/128), 512, GEMM_SMEM>>>(xh, xl, wkh, wkl, kp, MT_, HKV_*HD_, D_);
    gemm_mma<<<dim3((HKV_*HD_)/128, MT_/128), 512, GEMM_SMEM>>>(xh, xl, wvh, wvl, vp, MT_, HKV_*HD_, D_);

    // per-head RMSNorm + RoPE (+gain for q), layout to (b,h,t,d)
    rmsnorm_rope<<<(B_*T_*H_)/4, 128>>>(qp, qh, qg, H_);
    rmsnorm_rope<<<(B_*T_*HKV_)/4, 128>>>(kp, kh, (const float*)nullptr, HKV_);
    transpose_v_kernel<<<(B_*T_*HKV_*HD_)/256, 256>>>();

    // GDN input normalization
    l2norm64<<<(B_*T_*HG_)/4, 128>>>(gq, qn);
    l2norm64<<<(B_*T_*HG_)/4, 128>>>(gk, kn);

    // causal attention -> g_y
    attn_kernel<<<dim3(T_/128 * 32), 128>>>();

    // output projection on tensor cores -> d_out
    split_bf16<<<(MT_*D_/4 + 255)/256, 256>>>(yb, yh, yl, MT_*D_/4);
    gemm_mma<<<dim3(D_/128, MT_/128), 512, GEMM_SMEM>>>(yh, yl, woh, wol, out, MT_, D_, D_);

    // GDN scan accumulates into d_out
    gdn_kernel<<<dim3(B_*HG_, DV_/32), 64>>>(gv, alpha, beta, out);
}

// round 4
// speedup vs baseline: 1.1798x; 1.0681x over previous
#include <cuda_runtime.h>
#include <cuda_bf16.h>
#include <cstdint>

// ---------------- problem constants ----------------
static constexpr int B_  = 2;
static constexpr int T_  = 1024;
static constexpr int D_  = 1024;
static constexpr int H_  = 16;
static constexpr int HKV_ = 4;
static constexpr int HD_ = 64;
static constexpr int HG_ = 8;
static constexpr int DV_ = 128;

static constexpr int MT_ = B_*T_;       // 2048 rows
static constexpr int NQKV_ = D_ + 2*HKV_*HD_;   // 1536 fused output cols

// ---------------- scratch (static device arrays; no allocation) ----------------
__device__ float g_qkv[MT_*NQKV_];        // fused projection out [row][1536]
__device__ float g_q [B_*H_*T_*HD_];
__device__ float g_k [B_*HKV_*T_*HD_];
__device__ float g_v [B_*HKV_*T_*HD_];
__device__ float g_y [B_*T_*D_];
__device__ float g_qn[B_*T_*HG_*64];
__device__ float g_kn[B_*T_*HG_*64];

// bf16 split-precision planes
__device__ __nv_bfloat16 g_xh[MT_*D_],  g_xl[MT_*D_];
__device__ __nv_bfloat16 g_wh[NQKV_*D_], g_wl[NQKV_*D_];   // fused Wq|Wk|Wv
__device__ __nv_bfloat16 g_woh[D_*D_],  g_wol[D_*D_];
__device__ __nv_bfloat16 g_yh[MT_*D_],  g_yl[MT_*D_];

// ---------------- small PTX helpers (baseline ISA only) ----------------
__device__ __forceinline__ uint32_t smem_u32(const void* p) {
    uint32_t a;
    asm("{ .reg .u64 t; cvta.to.shared.u64 t, %1; cvt.u32.u64 %0, t; }" : "=r"(a) : "l"(p));
    return a;
}
__device__ __forceinline__ void ldsm4(uint32_t (&r)[4], uint32_t addr) {
    asm volatile("ldmatrix.sync.aligned.m8n8.x4.shared.b16 {%0,%1,%2,%3}, [%4];"
        : "=r"(r[0]), "=r"(r[1]), "=r"(r[2]), "=r"(r[3]) : "r"(addr));
}
__device__ __forceinline__ void mma16816(float (&d)[4], const uint32_t (&a)[4],
                                         const uint32_t* b) {
    asm volatile("mma.sync.aligned.m16n8k16.row.col.f32.bf16.bf16.f32 "
        "{%0,%1,%2,%3}, {%4,%5,%6,%7}, {%8,%9}, {%0,%1,%2,%3};"
        : "+f"(d[0]), "+f"(d[1]), "+f"(d[2]), "+f"(d[3])
        : "r"(a[0]), "r"(a[1]), "r"(a[2]), "r"(a[3]), "r"(b[0]), "r"(b[1]));
}
__device__ __forceinline__ void cp16(uint32_t saddr, const void* gaddr) {
    asm volatile("cp.async.cg.shared.global [%0], [%1], 16;" :: "r"(saddr), "l"(gaddr));
}
#define CP_COMMIT() asm volatile("cp.async.commit_group;" ::: "memory")
#define CP_WAIT(n)  asm volatile("cp.async.wait_group %0;" :: "n"(n) : "memory")

// ---------------- fp32 -> bf16 hi/lo split ----------------
__device__ __forceinline__ void split4(float4 v, __nv_bfloat16* hi, __nv_bfloat16* lo, int i)
{
    __nv_bfloat16 h0 = __float2bfloat16(v.x), h1 = __float2bfloat16(v.y);
    __nv_bfloat16 h2 = __float2bfloat16(v.z), h3 = __float2bfloat16(v.w);
    __nv_bfloat16 l0 = __float2bfloat16(v.x - __bfloat162float(h0));
    __nv_bfloat16 l1 = __float2bfloat16(v.y - __bfloat162float(h1));
    __nv_bfloat16 l2 = __float2bfloat16(v.z - __bfloat162float(h2));
    __nv_bfloat16 l3 = __float2bfloat16(v.w - __bfloat162float(h3));
    ((__nv_bfloat162*)hi)[2*i]   = __nv_bfloat162(h0, h1);
    ((__nv_bfloat162*)hi)[2*i+1] = __nv_bfloat162(h2, h3);
    ((__nv_bfloat162*)lo)[2*i]   = __nv_bfloat162(l0, l1);
    ((__nv_bfloat162*)lo)[2*i+1] = __nv_bfloat162(l2, l3);
}

__global__ void split_bf16(const float* __restrict__ src,
                           __nv_bfloat16* __restrict__ hi,
                           __nv_bfloat16* __restrict__ lo, int n4)
{
    int i = blockIdx.x * 256 + threadIdx.x;
    if (i >= n4) return;
    split4(((const float4*)src)[i], hi, lo, i);
}

// fused Wq|Wk|Wv split into one [1536 x 1024] buffer
__global__ void split_w_qkv(const float* __restrict__ Wq, const float* __restrict__ Wk,
                            const float* __restrict__ Wv,
                            __nv_bfloat16* __restrict__ hi, __nv_bfloat16* __restrict__ lo)
{
    int i = blockIdx.x * 256 + threadIdx.x;      // float4 index over 1536x1024
    int e = i * 4;
    int row = e >> 10, col = e & 1023;
    const float* src;
    if (row < D_)               src = Wq + (size_t)row * D_ + col;
    else if (row < D_ + 256)    src = Wk + (size_t)(row - D_) * D_ + col;
    else                        src = Wv + (size_t)(row - D_ - 256) * D_ + col;
    split4(*(const float4*)src, hi, lo, i);
}

// ---------------- mma.sync bf16x2-split GEMM ----------------
// C[M,N] = A[M,K] @ B[N,K]^T, near-fp32. CTA tile 128x128, K-chunk 32, 3-stage.
static constexpr int ROWSTRIDE = 40;                 // bf16 elems (80B rows, conflict-free)
static constexpr int PLANE_B = 128 * ROWSTRIDE * 2;  // 10240 B
static constexpr int STAGE_B = 4 * PLANE_B;          // 40960 B
static constexpr int NSTAGE  = 3;
static constexpr int GEMM_SMEM = NSTAGE * STAGE_B;   // 122880 B

__global__ void __launch_bounds__(512) gemm_mma(
    const __nv_bfloat16* __restrict__ Ah, const __nv_bfloat16* __restrict__ Al,
    const __nv_bfloat16* __restrict__ Bh, const __nv_bfloat16* __restrict__ Bl,
    float* __restrict__ C, int M, int N, int K)
{
    extern __shared__ __align__(128) char smem[];
    const uint32_t sb = smem_u32(smem);
    const int tid = threadIdx.x;
    const int wid = tid >> 5, lane = tid & 31;
    const int wr = wid & 3, wc = wid >> 2;           // 4x4 warp grid
    const int m0 = blockIdx.y * 128;
    const int n0 = blockIdx.x * 128;
    const int NC = K >> 5;                           // K chunks of 32

    const int lrow = tid >> 2, lc16 = tid & 3;
    const uint32_t soff = (uint32_t)(lrow * (ROWSTRIDE*2) + lc16 * 16);
    const size_t gaoff = (size_t)(m0 + lrow) * K + lc16 * 8;
    const size_t gboff = (size_t)(n0 + lrow) * K + lc16 * 8;

    auto issue = [&](int kc) {
        uint32_t sd = sb + (kc % NSTAGE) * STAGE_B + soff;
        const int ko = kc * 32;
        cp16(sd + 0*PLANE_B, Ah + gaoff + ko);
        cp16(sd + 1*PLANE_B, Al + gaoff + ko);
        cp16(sd + 2*PLANE_B, Bh + gboff + ko);
        cp16(sd + 3*PLANE_B, Bl + gboff + ko);
        CP_COMMIT();
    };

    float acc[2][4][4];
#pragma unroll
    for (int mt = 0; mt < 2; mt++)
#pragma unroll
        for (int nt = 0; nt < 4; nt++)
#pragma unroll
            for (int j = 0; j < 4; j++) acc[mt][nt][j] = 0.f;

    issue(0);
    if (NC > 1) issue(1);

    const int lr = lane & 15, lchi = lane >> 4;

    for (int c = 0; c < NC; c++) {
        if (c + 1 < NC) { CP_WAIT(1); } else { CP_WAIT(0); }
        __syncthreads();
        if (c + 2 < NC) issue(c + 2);                // overwrites stage (c-1)%3: safe
        const uint32_t st = sb + (c % NSTAGE) * STAGE_B;
#pragma unroll
        for (int ks = 0; ks < 2; ks++) {
            const int koff = ks * 16 + lchi * 8;
            uint32_t aH[2][4], aL[2][4], bH[4][2], bL[4][2];
#pragma unroll
            for (int mt = 0; mt < 2; mt++) {
                uint32_t ro = (uint32_t)(((wr*32 + mt*16 + lr) * ROWSTRIDE + koff) * 2);
                ldsm4(aH[mt], st + 0*PLANE_B + ro);
                ldsm4(aL[mt], st + 1*PLANE_B + ro);
            }
#pragma unroll
            for (int np = 0; np < 2; np++) {
                uint32_t ro = (uint32_t)(((wc*32 + np*16 + lr) * ROWSTRIDE + koff) * 2);
                uint32_t t[4];
                ldsm4(t, st + 2*PLANE_B + ro);
                bH[np*2+0][0] = t[0]; bH[np*2+0][1] = t[2];
                bH[np*2+1][0] = t[1]; bH[np*2+1][1] = t[3];
                ldsm4(t, st + 3*PLANE_B + ro);
                bL[np*2+0][0] = t[0]; bL[np*2+0][1] = t[2];
                bL[np*2+1][0] = t[1]; bL[np*2+1][1] = t[3];
            }
#pragma unroll
            for (int mt = 0; mt < 2; mt++)
#pragma unroll
                for (int nt = 0; nt < 4; nt++) {
                    mma16816(acc[mt][nt], aH[mt], bH[nt]);
                    mma16816(acc[mt][nt], aH[mt], bL[nt]);
                    mma16816(acc[mt][nt], aL[mt], bH[nt]);
                }
        }
        __syncthreads();
    }

    // epilogue
    const int er = m0 + wr*32 + (lane >> 2);
    const int ec = n0 + wc*32 + (lane & 3) * 2;
#pragma unroll
    for (int mt = 0; mt < 2; mt++)
#pragma unroll
        for (int nt = 0; nt < 4; nt++) {
            float* p0 = C + (size_t)(er + mt*16) * N + ec + nt*8;
            float* p1 = C + (size_t)(er + mt*16 + 8) * N + ec + nt*8;
            *(float2*)p0 = make_float2(acc[mt][nt][0], acc[mt][nt][1]);
            *(float2*)p1 = make_float2(acc[mt][nt][2], acc[mt][nt][3]);
        }
}

// ---------------- RMSNorm + RoPE (+gain), from fused qkv to (b,h,t,d) ----------------
__global__ void rmsnorm_rope(const float* __restrict__ src, int colofs,
                             float* __restrict__ dst,
                             const float* __restrict__ gain, int nheads)
{
    int warp = threadIdx.x >> 5, lane = threadIdx.x & 31;
    int item = blockIdx.x*4 + warp;              // (b*T+t)*nheads + h
    int h = item % nheads;
    int row = item / nheads;                     // b*T + t
    int tpos = row & (T_-1);
    int b = row >> 10;
    const float* p = src + (size_t)row * NQKV_ + colofs + h*64;
    float x1 = p[lane], x2 = p[lane+32];
    float ss = x1*x1 + x2*x2;
#pragma unroll
    for (int o = 16; o > 0; o >>= 1) ss += __shfl_xor_sync(0xffffffffu, ss, o);
    float r = rsqrtf(ss*(1.0f/64.0f) + 1e-6f);
    x1 *= r; x2 *= r;
    float invf = expf(-(float)lane * (9.210340371976184f/32.0f));
    float ang = (float)tpos * invf;
    float sv, cv;
    sincosf(ang, &sv, &cv);
    float o1 = x1*cv + x2*sv;
    float o2 = x2*cv - x1*sv;
    float g = gain ? gain[h] : 1.0f;
    float* q = dst + (((size_t)(b*nheads + h)*T_) + tpos)*64;
    q[lane]    = o1*g;
    q[lane+32] = o2*g;
}

__global__ void transpose_v_kernel()
{
    int idx = blockIdx.x*256 + threadIdx.x;      // (b,t,h,d) over 2*1024*4*64
    int d = idx & 63;
    int h = (idx >> 6) & 3;
    int t = (idx >> 8) & 1023;
    int b = idx >> 18;
    int row = b*T_ + t;
    g_v[(((size_t)(b*HKV_ + h))*T_ + t)*64 + d] =
        g_qkv[(size_t)row * NQKV_ + (D_ + 256) + h*64 + d];
}

__global__ void l2norm64(const float* __restrict__ src, float* __restrict__ dst)
{
    int warp = threadIdx.x >> 5, lane = threadIdx.x & 31;
    int item = blockIdx.x*4 + warp;
    const float* p = src + (size_t)item*64;
    float x1 = p[lane], x2 = p[lane+32];
    float ss = x1*x1 + x2*x2;
#pragma unroll
    for (int o = 16; o > 0; o >>= 1) ss += __shfl_xor_sync(0xffffffffu, ss, o);
    float n = sqrtf(ss);
    float r = 1.0f / fmaxf(n, 1e-6f);
    dst[(size_t)item*64 + lane]      = x1*r;
    dst[(size_t)item*64 + lane + 32] = x2*r;
}

// ---------------- causal flash attention (heavy blocks first) ----------------
__global__ void __launch_bounds__(128, 1) attn_kernel()
{
    const int qt = 7 - (blockIdx.x >> 5);
    const int hb = blockIdx.x & 31;
    const int h = hb & 15, b = hb >> 4;
    const int qi = qt*128 + threadIdx.x;
    __shared__ float Ks[32][64];
    __shared__ float Vs[32][64];
    const float* qp = g_q + (((size_t)(b*H_ + h)*T_) + qi)*64;
    const float* kb = g_k + ((size_t)(b*HKV_ + (h>>2))*T_)*64;
    const float* vb = g_v + ((size_t)(b*HKV_ + (h>>2))*T_)*64;

    float q[64];
#pragma unroll
    for (int c = 0; c < 16; c++) {
        float4 v4 = ((const float4*)qp)[c];
        q[c*4+0]=v4.x; q[c*4+1]=v4.y; q[c*4+2]=v4.z; q[c*4+3]=v4.w;
    }
    float acc[64];
#pragma unroll
    for (int c = 0; c < 64; c++) acc[c] = 0.f;
    float m = -1e30f, l = 0.f;

    const int ntiles = (qt + 1) * 4;
    for (int tile = 0; tile < ntiles; ++tile) {
        __syncthreads();
#pragma unroll
        for (int i = 0; i < 4; i++) {
            int f = threadIdx.x + i*128;
            int row = f >> 4, c4 = f & 15;
            const float4* kg = (const float4*)(kb + (size_t)(tile*32 + row)*64);
            const float4* vg = (const float4*)(vb + (size_t)(tile*32 + row)*64);
            *(float4*)&Ks[row][c4*4] = kg[c4];
            *(float4*)&Vs[row][c4*4] = vg[c4];
        }
        __syncthreads();

        float s[32];
        float mt = -1e30f;
#pragma unroll
        for (int j = 0; j < 32; j++) {
            float d0=0.f,d1=0.f,d2=0.f,d3=0.f;
            const float4* kr = (const float4*)&Ks[j][0];
#pragma unroll
            for (int c = 0; c < 16; c++) {
                float4 kv = kr[c];
                d0 = fmaf(q[c*4+0], kv.x, d0);
                d1 = fmaf(q[c*4+1], kv.y, d1);
                d2 = fmaf(q[c*4+2], kv.z, d2);
                d3 = fmaf(q[c*4+3], kv.w, d3);
            }
            float sc = ((d0+d1)+(d2+d3)) * 0.125f;
            int kj = tile*32 + j;
            s[j] = (kj <= qi) ? sc : -1e30f;
            mt = fmaxf(mt, s[j]);
        }
        float mnew = fmaxf(m, mt);
        float corr = __expf(m - mnew);
        m = mnew;
        l *= corr;
#pragma unroll
        for (int c = 0; c < 64; c++) acc[c] *= corr;
#pragma unroll
        for (int j = 0; j < 32; j++) {
            float p = __expf(s[j] - mnew);
            l += p;
            const float4* vr = (const float4*)&Vs[j][0];
#pragma unroll
            for (int c = 0; c < 16; c++) {
                float4 vv = vr[c];
                acc[c*4+0] = fmaf(p, vv.x, acc[c*4+0]);
                acc[c*4+1] = fmaf(p, vv.y, acc[c*4+1]);
                acc[c*4+2] = fmaf(p, vv.z, acc[c*4+2]);
                acc[c*4+3] = fmaf(p, vv.w, acc[c*4+3]);
            }
        }
    }
    float inv = 1.f / l;
    float* op = g_y + ((size_t)(b*T_ + qi)*D_) + h*64;
#pragma unroll
    for (int c = 0; c < 16; c++) {
        float4 o = make_float4(acc[c*4+0]*inv, acc[c*4+1]*inv,
                               acc[c*4+2]*inv, acc[c*4+3]*inv);
        ((float4*)op)[c] = o;
    }
}

// ---------------- gated delta net scan (adds into out) ----------------
__global__ void __launch_bounds__(64) gdn_kernel(const float* __restrict__ gv,
    const float* __restrict__ alpha, const float* __restrict__ beta,
    float* __restrict__ out)
{
    const int b = blockIdx.x >> 3;
    const int h = blockIdx.x & 7;
    const int tid = threadIdx.x;
    const int v = blockIdx.y*32 + (tid >> 1);
    const int half = tid & 1;
    __shared__ float ks[64], qs[64];
    float S[32];
#pragma unroll
    for (int i = 0; i < 32; i++) S[i] = 0.f;

    const float* kptr = g_kn + ((size_t)b*T_*HG_ + h)*64 + tid;
    const float* qptr = g_qn + ((size_t)b*T_*HG_ + h)*64 + tid;
    const float* vptr = gv   + ((size_t)b*T_*HG_ + h)*128 + v;
    const float* aptr = alpha + (size_t)b*T_*HG_ + h;
    const float* bptr = beta  + (size_t)b*T_*HG_ + h;
    float* optr = out + (size_t)b*T_*D_ + h*DV_ + v;

    float pk = *kptr, pq = *qptr, pv = *vptr, pa = *aptr, pb = *bptr;

    for (int t = 0; t < T_; ++t) {
        __syncthreads();
        ks[tid] = pk; qs[tid] = pq;
        float a = pa, bb = pb, vt = pv;
        __syncthreads();
        if (t < T_-1) {
            kptr += HG_*64; qptr += HG_*64; vptr += HG_*128; aptr += HG_; bptr += HG_;
            pk = *kptr; pq = *qptr; pv = *vptr; pa = *aptr; pb = *bptr;
        }
        float kr[32];
#pragma unroll
        for (int c = 0; c < 8; c++) {
            float4 k4 = *(const float4*)&ks[half*32 + c*4];
            kr[c*4+0]=k4.x; kr[c*4+1]=k4.y; kr[c*4+2]=k4.z; kr[c*4+3]=k4.w;
        }
        float r0=0.f,r1=0.f,r2=0.f,r3=0.f;
#pragma unroll
        for (int c = 0; c < 8; c++) {
            r0 = fmaf(kr[c*4+0], S[c*4+0], r0);
            r1 = fmaf(kr[c*4+1], S[c*4+1], r1);
            r2 = fmaf(kr[c*4+2], S[c*4+2], r2);
            r3 = fmaf(kr[c*4+3], S[c*4+3], r3);
        }
        float kS = (r0+r1)+(r2+r3);
        kS += __shfl_xor_sync(0xffffffffu, kS, 1);
        float coef = fmaf(-a*bb, kS, vt);
#pragma unroll
        for (int i = 0; i < 32; i++) S[i] = fmaf(coef, kr[i], a*S[i]);
        float o0=0.f,o1=0.f,o2=0.f,o3=0.f;
#pragma unroll
        for (int c = 0; c < 8; c++) {
            float4 q4 = *(const float4*)&qs[half*32 + c*4];
            o0 = fmaf(S[c*4+0], q4.x, o0);
            o1 = fmaf(S[c*4+1], q4.y, o1);
            o2 = fmaf(S[c*4+2], q4.z, o2);
            o3 = fmaf(S[c*4+3], q4.w, o3);
        }
        float o = (o0+o1)+(o2+o3);
        o += __shfl_xor_sync(0xffffffffu, o, 1);
        if (half == 0) *optr += o;
        optr += D_;
    }
}

// ---------------- launch ----------------
extern "C" void kernel_launch(void* const* d_in, const int* in_sizes, int n_in,
                              void* d_out, int out_size)
{
    const float* x     = (const float*)d_in[0];
    const float* Wq    = (const float*)d_in[1];
    const float* Wk    = (const float*)d_in[2];
    const float* Wv    = (const float*)d_in[3];
    const float* Wo    = (const float*)d_in[4];
    const float* qg    = (const float*)d_in[5];
    const float* gq    = (const float*)d_in[6];
    const float* gk    = (const float*)d_in[7];
    const float* gv    = (const float*)d_in[8];
    const float* alpha = (const float*)d_in[9];
    const float* beta  = (const float*)d_in[10];
    float* out = (float*)d_out;

    float *qkv,*qh,*kh,*yb,*qn,*kn;
    cudaGetSymbolAddress((void**)&qkv, g_qkv);
    cudaGetSymbolAddress((void**)&qh, g_q);
    cudaGetSymbolAddress((void**)&kh, g_k);
    cudaGetSymbolAddress((void**)&yb, g_y);
    cudaGetSymbolAddress((void**)&qn, g_qn);
    cudaGetSymbolAddress((void**)&kn, g_kn);

    __nv_bfloat16 *xh,*xl,*wh,*wl,*woh,*wol,*yh,*yl;
    cudaGetSymbolAddress((void**)&xh, g_xh);   cudaGetSymbolAddress((void**)&xl, g_xl);
    cudaGetSymbolAddress((void**)&wh, g_wh);   cudaGetSymbolAddress((void**)&wl, g_wl);
    cudaGetSymbolAddress((void**)&woh, g_woh); cudaGetSymbolAddress((void**)&wol, g_wol);
    cudaGetSymbolAddress((void**)&yh, g_yh);   cudaGetSymbolAddress((void**)&yl, g_yl);

    cudaFuncSetAttribute(gemm_mma, cudaFuncAttributeMaxDynamicSharedMemorySize, GEMM_SMEM);

    // 0: split x, 1: split fused W(qkv), 2: split Wo
    split_bf16<<<MT_*D_/4/256, 256>>>(x, xh, xl, MT_*D_/4);
    split_w_qkv<<<NQKV_*D_/4/256, 256>>>(Wq, Wk, Wv, wh, wl);
    split_bf16<<<D_*D_/4/256, 256>>>(Wo, woh, wol, D_*D_/4);

    // 3: fused QKV projection (lands at ncu capture index)
    gemm_mma<<<dim3(NQKV_/128, MT_/128), 512, GEMM_SMEM>>>(xh, xl, wh, wl, qkv, MT_, NQKV_, D_);

    // norm/rope/transpose from fused buffer
    rmsnorm_rope<<<(B_*T_*H_)/4, 128>>>(qkv, 0, qh, qg, H_);
    rmsnorm_rope<<<(B_*T_*HKV_)/4, 128>>>(qkv, D_, kh, (const float*)nullptr, HKV_);
    transpose_v_kernel<<<(B_*T_*HKV_*HD_)/256, 256>>>();

    // GDN input normalization
    l2norm64<<<(B_*T_*HG_)/4, 128>>>(gq, qn);
    l2norm64<<<(B_*T_*HG_)/4, 128>>>(gk, kn);

    // causal attention -> g_y
    attn_kernel<<<dim3(T_/128 * 32), 128>>>();

    // output projection -> d_out
    split_bf16<<<MT_*D_/4/256, 256>>>(yb, yh, yl, MT_*D_/4);
    gemm_mma<<<dim3(D_/128, MT_/128), 512, GEMM_SMEM>>>(yh, yl, woh, wol, out, MT_, D_, D_);

    // GDN scan accumulates into d_out
    gdn_kernel<<<dim3(B_*HG_, DV_/32), 64>>>(gv, alpha, beta, out);
}

// round 5
// speedup vs baseline: 1.2089x; 1.0247x over previous
#include <cuda_runtime.h>
#include <cuda_bf16.h>
#include <cstdint>

// ---------------- problem constants ----------------
static constexpr int B_  = 2;
static constexpr int T_  = 1024;
static constexpr int D_  = 1024;
static constexpr int H_  = 16;
static constexpr int HKV_ = 4;
static constexpr int HD_ = 64;
static constexpr int HG_ = 8;
static constexpr int DV_ = 128;

static constexpr int MT_ = B_*T_;               // 2048 rows
static constexpr int NQKV_ = D_ + 2*HKV_*HD_;   // 1536 fused output cols

// ---------------- scratch (static device arrays; no allocation) ----------------
__device__ float g_qkv[MT_*NQKV_];
__device__ float g_q [B_*H_*T_*HD_];
__device__ float g_k [B_*HKV_*T_*HD_];
__device__ float g_v [B_*HKV_*T_*HD_];
__device__ float g_y [B_*T_*D_];
__device__ float g_qn[B_*T_*HG_*64];
__device__ float g_kn[B_*T_*HG_*64];

// split-K attention partials: [p(32)][qt(8)][ch(4)][q(128)]
__device__ float g_pm[32*8*4*128];
__device__ float g_pl[32*8*4*128];
__device__ float g_pacc[32*8*4*128*64];   // 33.5 MB

// bf16 split-precision planes
__device__ __nv_bfloat16 g_xh[MT_*D_],  g_xl[MT_*D_];
__device__ __nv_bfloat16 g_wh[NQKV_*D_], g_wl[NQKV_*D_];
__device__ __nv_bfloat16 g_woh[D_*D_],  g_wol[D_*D_];
__device__ __nv_bfloat16 g_yh[MT_*D_],  g_yl[MT_*D_];

// ---------------- small PTX helpers ----------------
__device__ __forceinline__ uint32_t smem_u32(const void* p) {
    uint32_t a;
    asm("{ .reg .u64 t; cvta.to.shared.u64 t, %1; cvt.u32.u64 %0, t; }" : "=r"(a) : "l"(p));
    return a;
}
__device__ __forceinline__ void ldsm4(uint32_t (&r)[4], uint32_t addr) {
    asm volatile("ldmatrix.sync.aligned.m8n8.x4.shared.b16 {%0,%1,%2,%3}, [%4];"
        : "=r"(r[0]), "=r"(r[1]), "=r"(r[2]), "=r"(r[3]) : "r"(addr));
}
__device__ __forceinline__ void mma16816(float (&d)[4], const uint32_t (&a)[4],
                                         const uint32_t* b) {
    asm volatile("mma.sync.aligned.m16n8k16.row.col.f32.bf16.bf16.f32 "
        "{%0,%1,%2,%3}, {%4,%5,%6,%7}, {%8,%9}, {%0,%1,%2,%3};"
        : "+f"(d[0]), "+f"(d[1]), "+f"(d[2]), "+f"(d[3])
        : "r"(a[0]), "r"(a[1]), "r"(a[2]), "r"(a[3]), "r"(b[0]), "r"(b[1]));
}
__device__ __forceinline__ void cp16(uint32_t saddr, const void* gaddr) {
    asm volatile("cp.async.cg.shared.global [%0], [%1], 16;" :: "r"(saddr), "l"(gaddr));
}
#define CP_COMMIT() asm volatile("cp.async.commit_group;" ::: "memory")
#define CP_WAIT(n)  asm volatile("cp.async.wait_group %0;" :: "n"(n) : "memory")

// ---------------- fp32 -> bf16 hi/lo split ----------------
__device__ __forceinline__ void split4(float4 v, __nv_bfloat16* hi, __nv_bfloat16* lo, int i)
{
    __nv_bfloat16 h0 = __float2bfloat16(v.x), h1 = __float2bfloat16(v.y);
    __nv_bfloat16 h2 = __float2bfloat16(v.z), h3 = __float2bfloat16(v.w);
    __nv_bfloat16 l0 = __float2bfloat16(v.x - __bfloat162float(h0));
    __nv_bfloat16 l1 = __float2bfloat16(v.y - __bfloat162float(h1));
    __nv_bfloat16 l2 = __float2bfloat16(v.z - __bfloat162float(h2));
    __nv_bfloat16 l3 = __float2bfloat16(v.w - __bfloat162float(h3));
    ((__nv_bfloat162*)hi)[2*i]   = __nv_bfloat162(h0, h1);
    ((__nv_bfloat162*)hi)[2*i+1] = __nv_bfloat162(h2, h3);
    ((__nv_bfloat162*)lo)[2*i]   = __nv_bfloat162(l0, l1);
    ((__nv_bfloat162*)lo)[2*i+1] = __nv_bfloat162(l2, l3);
}

__global__ void split_bf16(const float* __restrict__ src,
                           __nv_bfloat16* __restrict__ hi,
                           __nv_bfloat16* __restrict__ lo, int n4)
{
    int i = blockIdx.x * 256 + threadIdx.x;
    if (i >= n4) return;
    split4(((const float4*)src)[i], hi, lo, i);
}

__global__ void split_w_qkv(const float* __restrict__ Wq, const float* __restrict__ Wk,
                            const float* __restrict__ Wv,
                            __nv_bfloat16* __restrict__ hi, __nv_bfloat16* __restrict__ lo)
{
    int i = blockIdx.x * 256 + threadIdx.x;
    int e = i * 4;
    int row = e >> 10, col = e & 1023;
    const float* src;
    if (row < D_)               src = Wq + (size_t)row * D_ + col;
    else if (row < D_ + 256)    src = Wk + (size_t)(row - D_) * D_ + col;
    else                        src = Wv + (size_t)(row - D_ - 256) * D_ + col;
    split4(*(const float4*)src, hi, lo, i);
}

// ---------------- mma.sync bf16x2-split GEMM (unchanged) ----------------
static constexpr int ROWSTRIDE = 40;
static constexpr int PLANE_B = 128 * ROWSTRIDE * 2;
static constexpr int STAGE_B = 4 * PLANE_B;
static constexpr int NSTAGE  = 3;
static constexpr int GEMM_SMEM = NSTAGE * STAGE_B;

__global__ void __launch_bounds__(512) gemm_mma(
    const __nv_bfloat16* __restrict__ Ah, const __nv_bfloat16* __restrict__ Al,
    const __nv_bfloat16* __restrict__ Bh, const __nv_bfloat16* __restrict__ Bl,
    float* __restrict__ C, int M, int N, int K)
{
    extern __shared__ __align__(128) char smem[];
    const uint32_t sb = smem_u32(smem);
    const int tid = threadIdx.x;
    const int wid = tid >> 5, lane = tid & 31;
    const int wr = wid & 3, wc = wid >> 2;
    const int m0 = blockIdx.y * 128;
    const int n0 = blockIdx.x * 128;
    const int NC = K >> 5;

    const int lrow = tid >> 2, lc16 = tid & 3;
    const uint32_t soff = (uint32_t)(lrow * (ROWSTRIDE*2) + lc16 * 16);
    const size_t gaoff = (size_t)(m0 + lrow) * K + lc16 * 8;
    const size_t gboff = (size_t)(n0 + lrow) * K + lc16 * 8;

    auto issue = [&](int kc) {
        uint32_t sd = sb + (kc % NSTAGE) * STAGE_B + soff;
        const int ko = kc * 32;
        cp16(sd + 0*PLANE_B, Ah + gaoff + ko);
        cp16(sd + 1*PLANE_B, Al + gaoff + ko);
        cp16(sd + 2*PLANE_B, Bh + gboff + ko);
        cp16(sd + 3*PLANE_B, Bl + gboff + ko);
        CP_COMMIT();
    };

    float acc[2][4][4];
#pragma unroll
    for (int mt = 0; mt < 2; mt++)
#pragma unroll
        for (int nt = 0; nt < 4; nt++)
#pragma unroll
            for (int j = 0; j < 4; j++) acc[mt][nt][j] = 0.f;

    issue(0);
    if (NC > 1) issue(1);

    const int lr = lane & 15, lchi = lane >> 4;

    for (int c = 0; c < NC; c++) {
        if (c + 1 < NC) { CP_WAIT(1); } else { CP_WAIT(0); }
        __syncthreads();
        if (c + 2 < NC) issue(c + 2);
        const uint32_t st = sb + (c % NSTAGE) * STAGE_B;
#pragma unroll
        for (int ks = 0; ks < 2; ks++) {
            const int koff = ks * 16 + lchi * 8;
            uint32_t aH[2][4], aL[2][4], bH[4][2], bL[4][2];
#pragma unroll
            for (int mt = 0; mt < 2; mt++) {
                uint32_t ro = (uint32_t)(((wr*32 + mt*16 + lr) * ROWSTRIDE + koff) * 2);
                ldsm4(aH[mt], st + 0*PLANE_B + ro);
                ldsm4(aL[mt], st + 1*PLANE_B + ro);
            }
#pragma unroll
            for (int np = 0; np < 2; np++) {
                uint32_t ro = (uint32_t)(((wc*32 + np*16 + lr) * ROWSTRIDE + koff) * 2);
                uint32_t t[4];
                ldsm4(t, st + 2*PLANE_B + ro);
                bH[np*2+0][0] = t[0]; bH[np*2+0][1] = t[2];
                bH[np*2+1][0] = t[1]; bH[np*2+1][1] = t[3];
                ldsm4(t, st + 3*PLANE_B + ro);
                bL[np*2+0][0] = t[0]; bL[np*2+0][1] = t[2];
                bL[np*2+1][0] = t[1]; bL[np*2+1][1] = t[3];
            }
#pragma unroll
            for (int mt = 0; mt < 2; mt++)
#pragma unroll
                for (int nt = 0; nt < 4; nt++) {
                    mma16816(acc[mt][nt], aH[mt], bH[nt]);
                    mma16816(acc[mt][nt], aH[mt], bL[nt]);
                    mma16816(acc[mt][nt], aL[mt], bH[nt]);
                }
        }
        __syncthreads();
    }

    const int er = m0 + wr*32 + (lane >> 2);
    const int ec = n0 + wc*32 + (lane & 3) * 2;
#pragma unroll
    for (int mt = 0; mt < 2; mt++)
#pragma unroll
        for (int nt = 0; nt < 4; nt++) {
            float* p0 = C + (size_t)(er + mt*16) * N + ec + nt*8;
            float* p1 = C + (size_t)(er + mt*16 + 8) * N + ec + nt*8;
            *(float2*)p0 = make_float2(acc[mt][nt][0], acc[mt][nt][1]);
            *(float2*)p1 = make_float2(acc[mt][nt][2], acc[mt][nt][3]);
        }
}

// ---------------- RMSNorm + RoPE (+gain) ----------------
__global__ void rmsnorm_rope(const float* __restrict__ src, int colofs,
                             float* __restrict__ dst,
                             const float* __restrict__ gain, int nheads)
{
    int warp = threadIdx.x >> 5, lane = threadIdx.x & 31;
    int item = blockIdx.x*4 + warp;
    int h = item % nheads;
    int row = item / nheads;
    int tpos = row & (T_-1);
    int b = row >> 10;
    const float* p = src + (size_t)row * NQKV_ + colofs + h*64;
    float x1 = p[lane], x2 = p[lane+32];
    float ss = x1*x1 + x2*x2;
#pragma unroll
    for (int o = 16; o > 0; o >>= 1) ss += __shfl_xor_sync(0xffffffffu, ss, o);
    float r = rsqrtf(ss*(1.0f/64.0f) + 1e-6f);
    x1 *= r; x2 *= r;
    float invf = expf(-(float)lane * (9.210340371976184f/32.0f));
    float ang = (float)tpos * invf;
    float sv, cv;
    sincosf(ang, &sv, &cv);
    float o1 = x1*cv + x2*sv;
    float o2 = x2*cv - x1*sv;
    float g = gain ? gain[h] : 1.0f;
    float* q = dst + (((size_t)(b*nheads + h)*T_) + tpos)*64;
    q[lane]    = o1*g;
    q[lane+32] = o2*g;
}

__global__ void transpose_v_kernel()
{
    int idx = blockIdx.x*256 + threadIdx.x;
    int d = idx & 63;
    int h = (idx >> 6) & 3;
    int t = (idx >> 8) & 1023;
    int b = idx >> 18;
    int row = b*T_ + t;
    g_v[(((size_t)(b*HKV_ + h))*T_ + t)*64 + d] =
        g_qkv[(size_t)row * NQKV_ + (D_ + 256) + h*64 + d];
}

__global__ void l2norm64(const float* __restrict__ src, float* __restrict__ dst)
{
    int warp = threadIdx.x >> 5, lane = threadIdx.x & 31;
    int item = blockIdx.x*4 + warp;
    const float* p = src + (size_t)item*64;
    float x1 = p[lane], x2 = p[lane+32];
    float ss = x1*x1 + x2*x2;
#pragma unroll
    for (int o = 16; o > 0; o >>= 1) ss += __shfl_xor_sync(0xffffffffu, ss, o);
    float n = sqrtf(ss);
    float r = 1.0f / fmaxf(n, 1e-6f);
    dst[(size_t)item*64 + lane]      = x1*r;
    dst[(size_t)item*64 + lane + 32] = x2*r;
}

// ---------------- split-K causal flash attention: partials ----------------
// 640 blocks: (b,h) x 20 (qt,chunk) units; chunk = up to 256 keys.
__global__ void __launch_bounds__(128, 1) attn_part()
{
    const int p = blockIdx.x / 20;
    int w = blockIdx.x % 20;
    const int b = p >> 4, h = p & 15;
    int qt = 0;
#pragma unroll
    for (int qq = 0; qq < 8; qq++) {
        int n = (qq + 2) >> 1;
        if (w < n) { qt = qq; break; }
        w -= n;
    }
    const int ch = w;
    const int qi = qt*128 + threadIdx.x;
    const int k0 = ch * 256;
    const int kend = min(k0 + 256, (qt+1)*128);
    const int ntiles = (kend - k0) >> 5;

    __shared__ float Ks[32][64];
    __shared__ float Vs[32][64];
    const float* qp = g_q + (((size_t)(b*H_ + h)*T_) + qi)*64;
    const float* kb = g_k + ((size_t)(b*HKV_ + (h>>2))*T_)*64;
    const float* vb = g_v + ((size_t)(b*HKV_ + (h>>2))*T_)*64;

    float q[64];
#pragma unroll
    for (int c = 0; c < 16; c++) {
        float4 v4 = ((const float4*)qp)[c];
        q[c*4+0]=v4.x; q[c*4+1]=v4.y; q[c*4+2]=v4.z; q[c*4+3]=v4.w;
    }
    float acc[64];
#pragma unroll
    for (int c = 0; c < 64; c++) acc[c] = 0.f;
    float m = -1e30f, l = 0.f;

    for (int tile = 0; tile < ntiles; ++tile) {
        const int krow0 = k0 + tile*32;
        __syncthreads();
#pragma unroll
        for (int i = 0; i < 4; i++) {
            int f = threadIdx.x + i*128;
            int row = f >> 4, c4 = f & 15;
            const float4* kg = (const float4*)(kb + (size_t)(krow0 + row)*64);
            const float4* vg = (const float4*)(vb + (size_t)(krow0 + row)*64);
            *(float4*)&Ks[row][c4*4] = kg[c4];
            *(float4*)&Vs[row][c4*4] = vg[c4];
        }
        __syncthreads();

        float s[32];
        float mt = -1e30f;
#pragma unroll
        for (int j = 0; j < 32; j++) {
            float d0=0.f,d1=0.f,d2=0.f,d3=0.f;
            const float4* kr = (const float4*)&Ks[j][0];
#pragma unroll
            for (int c = 0; c < 16; c++) {
                float4 kv = kr[c];
                d0 = fmaf(q[c*4+0], kv.x, d0);
                d1 = fmaf(q[c*4+1], kv.y, d1);
                d2 = fmaf(q[c*4+2], kv.z, d2);
                d3 = fmaf(q[c*4+3], kv.w, d3);
            }
            float sc = ((d0+d1)+(d2+d3)) * 0.125f;
            int kj = krow0 + j;
            s[j] = (kj <= qi) ? sc : -1e30f;
            mt = fmaxf(mt, s[j]);
        }
        float mnew = fmaxf(m, mt);
        float corr = __expf(m - mnew);
        m = mnew;
        l *= corr;
#pragma unroll
        for (int c = 0; c < 64; c++) acc[c] *= corr;
#pragma unroll
        for (int j = 0; j < 32; j++) {
            float pw = __expf(s[j] - mnew);
            l += pw;
            const float4* vr = (const float4*)&Vs[j][0];
#pragma unroll
            for (int c = 0; c < 16; c++) {
                float4 vv = vr[c];
                acc[c*4+0] = fmaf(pw, vv.x, acc[c*4+0]);
                acc[c*4+1] = fmaf(pw, vv.y, acc[c*4+1]);
                acc[c*4+2] = fmaf(pw, vv.z, acc[c*4+2]);
                acc[c*4+3] = fmaf(pw, vv.w, acc[c*4+3]);
            }
        }
    }

    const int slot = ((p*8 + qt)*4 + ch)*128 + threadIdx.x;
    g_pm[slot] = m;
    g_pl[slot] = l;
    float* pa = g_pacc + (size_t)slot*64;
#pragma unroll
    for (int c = 0; c < 16; c++)
        ((float4*)pa)[c] = make_float4(acc[c*4+0], acc[c*4+1], acc[c*4+2], acc[c*4+3]);
}

// ---------------- split-K merge: one warp per query ----------------
__global__ void __launch_bounds__(256) attn_merge()
{
    const int gw = (blockIdx.x * 256 + threadIdx.x) >> 5;   // 0..32767
    const int lane = threadIdx.x & 31;
    const int qq = gw & 127;
    const int rest = gw >> 7;
    const int qt = rest & 7;
    const int p = rest >> 3;
    const int b = p >> 4, h = p & 15;
    const int nch = (qt + 2) >> 1;
    const int base = ((p*8 + qt)*4)*128 + qq;

    float mv[4], lv[4];
    float M = -1e30f;
#pragma unroll
    for (int c = 0; c < 4; c++) {
        if (c < nch) {
            mv[c] = g_pm[base + c*128];
            lv[c] = g_pl[base + c*128];
            M = fmaxf(M, mv[c]);
        }
    }
    float L = 0.f, o1 = 0.f, o2 = 0.f;
#pragma unroll
    for (int c = 0; c < 4; c++) {
        if (c < nch) {
            float wgt = __expf(mv[c] - M);
            L = fmaf(wgt, lv[c], L);
            const float* pa = g_pacc + (size_t)(base + c*128)*64;
            o1 = fmaf(wgt, pa[lane], o1);
            o2 = fmaf(wgt, pa[lane+32], o2);
        }
    }
    float inv = 1.f / L;
    float* op = g_y + ((size_t)(b*T_ + qt*128 + qq))*D_ + h*64;
    op[lane]    = o1 * inv;
    op[lane+32] = o2 * inv;
}

// ---------------- gated delta net scan (single sync/step) ----------------
__global__ void __launch_bounds__(64) gdn_kernel(const float* __restrict__ gv,
    const float* __restrict__ alpha, const float* __restrict__ beta,
    float* __restrict__ out)
{
    const int b = blockIdx.x >> 3;
    const int h = blockIdx.x & 7;
    const int tid = threadIdx.x;
    const int v = blockIdx.y*32 + (tid >> 1);
    const int half = tid & 1;
    __shared__ float ks[2][64], qs[2][64];
    float S[32];
#pragma unroll
    for (int i = 0; i < 32; i++) S[i] = 0.f;

    const float* kptr = g_kn + ((size_t)b*T_*HG_ + h)*64 + tid;
    const float* qptr = g_qn + ((size_t)b*T_*HG_ + h)*64 + tid;
    const float* vptr = gv   + ((size_t)b*T_*HG_ + h)*128 + v;
    const float* aptr = alpha + (size_t)b*T_*HG_ + h;
    const float* bptr = beta  + (size_t)b*T_*HG_ + h;
    float* optr = out + (size_t)b*T_*D_ + h*DV_ + v;

    const int SK = HG_*64, SV = HG_*128, SS = HG_;

    // t=0 into buffer 0
    ks[0][tid] = kptr[0];
    qs[0][tid] = qptr[0];
    float cv = vptr[0], ca = aptr[0], cb = bptr[0];
    // prefetch t=1
    float nk = kptr[SK], nq = qptr[SK];
    float nv = vptr[SV], na = aptr[SS], nb = bptr[SS];
    __syncthreads();

    for (int t = 0; t < T_; ++t) {
        const int buf = t & 1;
        if (t + 1 < T_) {
            ks[buf^1][tid] = nk;
            qs[buf^1][tid] = nq;
        }
        const float a = ca, bb = cb, vt = cv;
        // prefetch t+2 (k/q) and shift scalars
        if (t + 2 < T_) {
            nk = kptr[(size_t)(t+2)*SK];
            nq = qptr[(size_t)(t+2)*SK];
        }
        cv = nv; ca = na; cb = nb;
        if (t + 2 < T_) {
            nv = vptr[(size_t)(t+2)*SV];
            na = aptr[(size_t)(t+2)*SS];
            nb = bptr[(size_t)(t+2)*SS];
        }

        float kr[32];
#pragma unroll
        for (int c = 0; c < 8; c++) {
            float4 k4 = *(const float4*)&ks[buf][half*32 + c*4];
            kr[c*4+0]=k4.x; kr[c*4+1]=k4.y; kr[c*4+2]=k4.z; kr[c*4+3]=k4.w;
        }
        float r0=0.f,r1=0.f,r2=0.f,r3=0.f;
#pragma unroll
        for (int c = 0; c < 8; c++) {
            r0 = fmaf(kr[c*4+0], S[c*4+0], r0);
            r1 = fmaf(kr[c*4+1], S[c*4+1], r1);
            r2 = fmaf(kr[c*4+2], S[c*4+2], r2);
            r3 = fmaf(kr[c*4+3], S[c*4+3], r3);
        }
        float kS = (r0+r1)+(r2+r3);
        kS += __shfl_xor_sync(0xffffffffu, kS, 1);
        float coef = fmaf(-a*bb, kS, vt);
#pragma unroll
        for (int i = 0; i < 32; i++) S[i] = fmaf(coef, kr[i], a*S[i]);
        float o0=0.f,o1=0.f,o2=0.f,o3=0.f;
#pragma unroll
        for (int c = 0; c < 8; c++) {
            float4 q4 = *(const float4*)&qs[buf][half*32 + c*4];
            o0 = fmaf(S[c*4+0], q4.x, o0);
            o1 = fmaf(S[c*4+1], q4.y, o1);
            o2 = fmaf(S[c*4+2], q4.z, o2);
            o3 = fmaf(S[c*4+3], q4.w, o3);
        }
        float o = (o0+o1)+(o2+o3);
        o += __shfl_xor_sync(0xffffffffu, o, 1);
        if (half == 0) optr[(size_t)t*D_] += o;
        __syncthreads();
    }
}

// ---------------- launch ----------------
extern "C" void kernel_launch(void* const* d_in, const int* in_sizes, int n_in,
                              void* d_out, int out_size)
{
    const float* x     = (const float*)d_in[0];
    const float* Wq    = (const float*)d_in[1];
    const float* Wk    = (const float*)d_in[2];
    const float* Wv    = (const float*)d_in[3];
    const float* Wo    = (const float*)d_in[4];
    const float* qg    = (const float*)d_in[5];
    const float* gq    = (const float*)d_in[6];
    const float* gk    = (const float*)d_in[7];
    const float* gv    = (const float*)d_in[8];
    const float* alpha = (const float*)d_in[9];
    const float* beta  = (const float*)d_in[10];
    float* out = (float*)d_out;

    float *qkv,*qh,*kh,*yb,*qn,*kn;
    cudaGetSymbolAddress((void**)&qkv, g_qkv);
    cudaGetSymbolAddress((void**)&qh, g_q);
    cudaGetSymbolAddress((void**)&kh, g_k);
    cudaGetSymbolAddress((void**)&yb, g_y);
    cudaGetSymbolAddress((void**)&qn, g_qn);
    cudaGetSymbolAddress((void**)&kn, g_kn);

    __nv_bfloat16 *xh,*xl,*wh,*wl,*woh,*wol,*yh,*yl;
    cudaGetSymbolAddress((void**)&xh, g_xh);   cudaGetSymbolAddress((void**)&xl, g_xl);
    cudaGetSymbolAddress((void**)&wh, g_wh);   cudaGetSymbolAddress((void**)&wl, g_wl);
    cudaGetSymbolAddress((void**)&woh, g_woh); cudaGetSymbolAddress((void**)&wol, g_wol);
    cudaGetSymbolAddress((void**)&yh, g_yh);   cudaGetSymbolAddress((void**)&yl, g_yl);

    cudaFuncSetAttribute(gemm_mma, cudaFuncAttributeMaxDynamicSharedMemorySize, GEMM_SMEM);

    // 0-2: splits
    split_bf16<<<MT_*D_/4/256, 256>>>(x, xh, xl, MT_*D_/4);
    split_w_qkv<<<NQKV_*D_/4/256, 256>>>(Wq, Wk, Wv, wh, wl);
    split_bf16<<<D_*D_/4/256, 256>>>(Wo, woh, wol, D_*D_/4);

    // 3: fused QKV projection (ncu capture index)
    gemm_mma<<<dim3(NQKV_/128, MT_/128), 512, GEMM_SMEM>>>(xh, xl, wh, wl, qkv, MT_, NQKV_, D_);

    // norm/rope/transpose
    rmsnorm_rope<<<(B_*T_*H_)/4, 128>>>(qkv, 0, qh, qg, H_);
    rmsnorm_rope<<<(B_*T_*HKV_)/4, 128>>>(qkv, D_, kh, (const float*)nullptr, HKV_);
    transpose_v_kernel<<<(B_*T_*HKV_*HD_)/256, 256>>>();

    // GDN input normalization
    l2norm64<<<(B_*T_*HG_)/4, 128>>>(gq, qn);
    l2norm64<<<(B_*T_*HG_)/4, 128>>>(gk, kn);

    // split-K attention -> partials -> merge into g_y
    attn_part<<<32*20, 128>>>();
    attn_merge<<<(32*8*128)/8, 256>>>();

    // output projection -> d_out
    split_bf16<<<MT_*D_/4/256, 256>>>(yb, yh, yl, MT_*D_/4);
    gemm_mma<<<dim3(D_/128, MT_/128), 512, GEMM_SMEM>>>(yh, yl, woh, wol, out, MT_, D_, D_);

    // GDN scan accumulates into d_out
    gdn_kernel<<<dim3(B_*HG_, DV_/32), 64>>>(gv, alpha, beta, out);
}

// round 6
// speedup vs baseline: 1.5045x; 1.2445x over previous
#include <cuda_runtime.h>
#include <cuda_bf16.h>
#include <cstdint>

// ---------------- problem constants ----------------
static constexpr int B_  = 2;
static constexpr int T_  = 1024;
static constexpr int D_  = 1024;
static constexpr int H_  = 16;
static constexpr int HKV_ = 4;
static constexpr int HD_ = 64;
static constexpr int HG_ = 8;
static constexpr int DV_ = 128;

static constexpr int MT_ = B_*T_;               // 2048 rows
static constexpr int NQKV_ = D_ + 2*HKV_*HD_;   // 1536

// ---------------- scratch ----------------
__device__ float g_qkv[MT_*NQKV_];
__device__ float g_y [B_*T_*D_];
__device__ float g_qn[B_*T_*HG_*64];
__device__ float g_kn[B_*T_*HG_*64];

// bf16 attention operand planes, layout (b,h,t,d)
__device__ __nv_bfloat16 g_qbh[B_*H_*T_*HD_],  g_qbl[B_*H_*T_*HD_];
__device__ __nv_bfloat16 g_kbh[B_*HKV_*T_*HD_], g_kbl[B_*HKV_*T_*HD_];
__device__ __nv_bfloat16 g_vbh[B_*HKV_*T_*HD_], g_vbl[B_*HKV_*T_*HD_];

// bf16 GEMM planes
__device__ __nv_bfloat16 g_xh[MT_*D_],  g_xl[MT_*D_];
__device__ __nv_bfloat16 g_wh[NQKV_*D_], g_wl[NQKV_*D_];
__device__ __nv_bfloat16 g_woh[D_*D_],  g_wol[D_*D_];
__device__ __nv_bfloat16 g_yh[MT_*D_],  g_yl[MT_*D_];

// ---------------- PTX helpers ----------------
__device__ __forceinline__ uint32_t smem_u32(const void* p) {
    uint32_t a;
    asm("{ .reg .u64 t; cvta.to.shared.u64 t, %1; cvt.u32.u64 %0, t; }" : "=r"(a) : "l"(p));
    return a;
}
__device__ __forceinline__ void ldsm4(uint32_t (&r)[4], uint32_t addr) {
    asm volatile("ldmatrix.sync.aligned.m8n8.x4.shared.b16 {%0,%1,%2,%3}, [%4];"
        : "=r"(r[0]), "=r"(r[1]), "=r"(r[2]), "=r"(r[3]) : "r"(addr));
}
__device__ __forceinline__ void ldsm4t(uint32_t (&r)[4], uint32_t addr) {
    asm volatile("ldmatrix.sync.aligned.m8n8.x4.trans.shared.b16 {%0,%1,%2,%3}, [%4];"
        : "=r"(r[0]), "=r"(r[1]), "=r"(r[2]), "=r"(r[3]) : "r"(addr));
}
__device__ __forceinline__ void mma16816(float (&d)[4], const uint32_t (&a)[4],
                                         const uint32_t* b) {
    asm volatile("mma.sync.aligned.m16n8k16.row.col.f32.bf16.bf16.f32 "
        "{%0,%1,%2,%3}, {%4,%5,%6,%7}, {%8,%9}, {%0,%1,%2,%3};"
        : "+f"(d[0]), "+f"(d[1]), "+f"(d[2]), "+f"(d[3])
        : "r"(a[0]), "r"(a[1]), "r"(a[2]), "r"(a[3]), "r"(b[0]), "r"(b[1]));
}
__device__ __forceinline__ void cp16(uint32_t saddr, const void* gaddr) {
    asm volatile("cp.async.cg.shared.global [%0], [%1], 16;" :: "r"(saddr), "l"(gaddr));
}
#define CP_COMMIT() asm volatile("cp.async.commit_group;" ::: "memory")
#define CP_WAIT(n)  asm volatile("cp.async.wait_group %0;" :: "n"(n) : "memory")

__device__ __forceinline__ uint32_t packb(float x, float y) {
    __nv_bfloat162 t(__float2bfloat16(x), __float2bfloat16(y));
    return *(uint32_t*)&t;
}

// ---------------- fp32 -> bf16 hi/lo split ----------------
__device__ __forceinline__ void split4(float4 v, __nv_bfloat16* hi, __nv_bfloat16* lo, int i)
{
    __nv_bfloat16 h0 = __float2bfloat16(v.x), h1 = __float2bfloat16(v.y);
    __nv_bfloat16 h2 = __float2bfloat16(v.z), h3 = __float2bfloat16(v.w);
    __nv_bfloat16 l0 = __float2bfloat16(v.x - __bfloat162float(h0));
    __nv_bfloat16 l1 = __float2bfloat16(v.y - __bfloat162float(h1));
    __nv_bfloat16 l2 = __float2bfloat16(v.z - __bfloat162float(h2));
    __nv_bfloat16 l3 = __float2bfloat16(v.w - __bfloat162float(h3));
    ((__nv_bfloat162*)hi)[2*i]   = __nv_bfloat162(h0, h1);
    ((__nv_bfloat162*)hi)[2*i+1] = __nv_bfloat162(h2, h3);
    ((__nv_bfloat162*)lo)[2*i]   = __nv_bfloat162(l0, l1);
    ((__nv_bfloat162*)lo)[2*i+1] = __nv_bfloat162(l2, l3);
}

__global__ void split_bf16(const float* __restrict__ src,
                           __nv_bfloat16* __restrict__ hi,
                           __nv_bfloat16* __restrict__ lo, int n4)
{
    int i = blockIdx.x * 256 + threadIdx.x;
    if (i >= n4) return;
    split4(((const float4*)src)[i], hi, lo, i);
}

__global__ void split_w_qkv(const float* __restrict__ Wq, const float* __restrict__ Wk,
                            const float* __restrict__ Wv,
                            __nv_bfloat16* __restrict__ hi, __nv_bfloat16* __restrict__ lo)
{
    int i = blockIdx.x * 256 + threadIdx.x;
    int e = i * 4;
    int row = e >> 10, col = e & 1023;
    const float* src;
    if (row < D_)               src = Wq + (size_t)row * D_ + col;
    else if (row < D_ + 256)    src = Wk + (size_t)(row - D_) * D_ + col;
    else                        src = Wv + (size_t)(row - D_ - 256) * D_ + col;
    split4(*(const float4*)src, hi, lo, i);
}

// ---------------- mma.sync bf16x2-split GEMM (proven, unchanged) ----------------
static constexpr int ROWSTRIDE = 40;
static constexpr int PLANE_B = 128 * ROWSTRIDE * 2;
static constexpr int STAGE_B = 4 * PLANE_B;
static constexpr int NSTAGE  = 3;
static constexpr int GEMM_SMEM = NSTAGE * STAGE_B;

__global__ void __launch_bounds__(512) gemm_mma(
    const __nv_bfloat16* __restrict__ Ah, const __nv_bfloat16* __restrict__ Al,
    const __nv_bfloat16* __restrict__ Bh, const __nv_bfloat16* __restrict__ Bl,
    float* __restrict__ C, int M, int N, int K)
{
    extern __shared__ __align__(128) char smem[];
    const uint32_t sb = smem_u32(smem);
    const int tid = threadIdx.x;
    const int wid = tid >> 5, lane = tid & 31;
    const int wr = wid & 3, wc = wid >> 2;
    const int m0 = blockIdx.y * 128;
    const int n0 = blockIdx.x * 128;
    const int NC = K >> 5;

    const int lrow = tid >> 2, lc16 = tid & 3;
    const uint32_t soff = (uint32_t)(lrow * (ROWSTRIDE*2) + lc16 * 16);
    const size_t gaoff = (size_t)(m0 + lrow) * K + lc16 * 8;
    const size_t gboff = (size_t)(n0 + lrow) * K + lc16 * 8;

    auto issue = [&](int kc) {
        uint32_t sd = sb + (kc % NSTAGE) * STAGE_B + soff;
        const int ko = kc * 32;
        cp16(sd + 0*PLANE_B, Ah + gaoff + ko);
        cp16(sd + 1*PLANE_B, Al + gaoff + ko);
        cp16(sd + 2*PLANE_B, Bh + gboff + ko);
        cp16(sd + 3*PLANE_B, Bl + gboff + ko);
        CP_COMMIT();
    };

    float acc[2][4][4];
#pragma unroll
    for (int mt = 0; mt < 2; mt++)
#pragma unroll
        for (int nt = 0; nt < 4; nt++)
#pragma unroll
            for (int j = 0; j < 4; j++) acc[mt][nt][j] = 0.f;

    issue(0);
    if (NC > 1) issue(1);

    const int lr = lane & 15, lchi = lane >> 4;

    for (int c = 0; c < NC; c++) {
        if (c + 1 < NC) { CP_WAIT(1); } else { CP_WAIT(0); }
        __syncthreads();
        if (c + 2 < NC) issue(c + 2);
        const uint32_t st = sb + (c % NSTAGE) * STAGE_B;
#pragma unroll
        for (int ks = 0; ks < 2; ks++) {
            const int koff = ks * 16 + lchi * 8;
            uint32_t aH[2][4], aL[2][4], bH[4][2], bL[4][2];
#pragma unroll
            for (int mt = 0; mt < 2; mt++) {
                uint32_t ro = (uint32_t)(((wr*32 + mt*16 + lr) * ROWSTRIDE + koff) * 2);
                ldsm4(aH[mt], st + 0*PLANE_B + ro);
                ldsm4(aL[mt], st + 1*PLANE_B + ro);
            }
#pragma unroll
            for (int np = 0; np < 2; np++) {
                uint32_t ro = (uint32_t)(((wc*32 + np*16 + lr) * ROWSTRIDE + koff) * 2);
                uint32_t t[4];
                ldsm4(t, st + 2*PLANE_B + ro);
                bH[np*2+0][0] = t[0]; bH[np*2+0][1] = t[2];
                bH[np*2+1][0] = t[1]; bH[np*2+1][1] = t[3];
                ldsm4(t, st + 3*PLANE_B + ro);
                bL[np*2+0][0] = t[0]; bL[np*2+0][1] = t[2];
                bL[np*2+1][0] = t[1]; bL[np*2+1][1] = t[3];
            }
#pragma unroll
            for (int mt = 0; mt < 2; mt++)
#pragma unroll
                for (int nt = 0; nt < 4; nt++) {
                    mma16816(acc[mt][nt], aH[mt], bH[nt]);
                    mma16816(acc[mt][nt], aH[mt], bL[nt]);
                    mma16816(acc[mt][nt], aL[mt], bH[nt]);
                }
        }
        __syncthreads();
    }

    const int er = m0 + wr*32 + (lane >> 2);
    const int ec = n0 + wc*32 + (lane & 3) * 2;
#pragma unroll
    for (int mt = 0; mt < 2; mt++)
#pragma unroll
        for (int nt = 0; nt < 4; nt++) {
            float* p0 = C + (size_t)(er + mt*16) * N + ec + nt*8;
            float* p1 = C + (size_t)(er + mt*16 + 8) * N + ec + nt*8;
            *(float2*)p0 = make_float2(acc[mt][nt][0], acc[mt][nt][1]);
            *(float2*)p1 = make_float2(acc[mt][nt][2], acc[mt][nt][3]);
        }
}

// ---------------- RMSNorm + RoPE -> bf16 hi/lo planes (b,h,t,d) ----------------
__global__ void rmsnorm_rope_bf16(const float* __restrict__ src, int colofs,
                                  __nv_bfloat16* __restrict__ dsth,
                                  __nv_bfloat16* __restrict__ dstl,
                                  const float* __restrict__ gain, int nheads)
{
    int warp = threadIdx.x >> 5, lane = threadIdx.x & 31;
    int item = blockIdx.x*4 + warp;
    int h = item % nheads;
    int row = item / nheads;
    int tpos = row & (T_-1);
    int b = row >> 10;
    const float* p = src + (size_t)row * NQKV_ + colofs + h*64;
    float x1 = p[lane], x2 = p[lane+32];
    float ss = x1*x1 + x2*x2;
#pragma unroll
    for (int o = 16; o > 0; o >>= 1) ss += __shfl_xor_sync(0xffffffffu, ss, o);
    float r = rsqrtf(ss*(1.0f/64.0f) + 1e-6f);
    x1 *= r; x2 *= r;
    float invf = expf(-(float)lane * (9.210340371976184f/32.0f));
    float ang = (float)tpos * invf;
    float sv, cv;
    sincosf(ang, &sv, &cv);
    float g = gain ? gain[h] : 1.0f;
    float o1 = (x1*cv + x2*sv) * g;
    float o2 = (x2*cv - x1*sv) * g;
    size_t base = (((size_t)(b*nheads + h)*T_) + tpos)*64;
    __nv_bfloat16 h1 = __float2bfloat16(o1), h2 = __float2bfloat16(o2);
    dsth[base + lane]      = h1;
    dsth[base + lane + 32] = h2;
    dstl[base + lane]      = __float2bfloat16(o1 - __bfloat162float(h1));
    dstl[base + lane + 32] = __float2bfloat16(o2 - __bfloat162float(h2));
}

// ---------------- V transpose -> bf16 hi/lo (b,h,t,d) ----------------
__global__ void transpose_v_bf16()
{
    int idx = blockIdx.x*256 + threadIdx.x;
    int d = idx & 63;
    int h = (idx >> 6) & 3;
    int t = (idx >> 8) & 1023;
    int b = idx >> 18;
    int row = b*T_ + t;
    float v = g_qkv[(size_t)row * NQKV_ + (D_ + 256) + h*64 + d];
    size_t o = (((size_t)(b*HKV_ + h))*T_ + t)*64 + d;
    __nv_bfloat16 hv = __float2bfloat16(v);
    g_vbh[o] = hv;
    g_vbl[o] = __float2bfloat16(v - __bfloat162float(hv));
}

__global__ void l2norm64(const float* __restrict__ src, float* __restrict__ dst)
{
    int warp = threadIdx.x >> 5, lane = threadIdx.x & 31;
    int item = blockIdx.x*4 + warp;
    const float* p = src + (size_t)item*64;
    float x1 = p[lane], x2 = p[lane+32];
    float ss = x1*x1 + x2*x2;
#pragma unroll
    for (int o = 16; o > 0; o >>= 1) ss += __shfl_xor_sync(0xffffffffu, ss, o);
    float n = sqrtf(ss);
    float r = 1.0f / fmaxf(n, 1e-6f);
    dst[(size_t)item*64 + lane]      = x1*r;
    dst[(size_t)item*64 + lane + 32] = x2*r;
}

// ---------------- flash attention on mma.sync ----------------
// smem: Q 64x72 bf16 x2 planes; K/V 32x72 x4 planes x3 stages. stride 72 elems.
static constexpr int ASTRIDE = 72;                 // elems (144B rows, ldmatrix conflict-free)
static constexpr int AQPL = 64 * ASTRIDE * 2;      // 9216
static constexpr int AKV0 = 2 * AQPL;              // 18432
static constexpr int AKVPL = 32 * ASTRIDE * 2;     // 4608
static constexpr int AKVSTG = 4 * AKVPL;           // 18432
static constexpr int ATT_SMEM = AKV0 + 3 * AKVSTG; // 73728

__global__ void __launch_bounds__(128, 1) attn_mma()
{
    extern __shared__ __align__(128) char sm[];
    const uint32_t sb = smem_u32(sm);
    const int bx = blockIdx.x;
    const int qt = 15 - (bx >> 5);                 // heavy first
    const int bh = bx & 31;
    const int b = bh >> 4, h = bh & 15;
    const int tid = threadIdx.x, w = tid >> 5, lane = tid & 31;
    const int gid = lane >> 2, tig = lane & 3;
    const int nkt = 2 * (qt + 1);
    const int row_base = qt*64 + w*16;

    const __nv_bfloat16* qsh = g_qbh + (((size_t)(b*H_ + h)*T_) + qt*64)*64;
    const __nv_bfloat16* qsl = g_qbl + (((size_t)(b*H_ + h)*T_) + qt*64)*64;
    const __nv_bfloat16* ksh = g_kbh + ((size_t)(b*HKV_ + (h>>2))*T_)*64;
    const __nv_bfloat16* ksl = g_kbl + ((size_t)(b*HKV_ + (h>>2))*T_)*64;
    const __nv_bfloat16* vsh = g_vbh + ((size_t)(b*HKV_ + (h>>2))*T_)*64;
    const __nv_bfloat16* vsl = g_vbl + ((size_t)(b*HKV_ + (h>>2))*T_)*64;

    // ---- load Q (2 planes) ----
#pragma unroll
    for (int i = 0; i < 8; i++) {
        int idx = tid + i*128;                     // 0..1023
        int plane = idx >> 9, rem = idx & 511;
        int r = rem >> 3, c = rem & 7;
        const __nv_bfloat16* src = plane ? qsl : qsh;
        cp16(sb + plane*AQPL + r*144 + c*16, src + r*64 + c*8);
    }
    CP_COMMIT();

    auto loadkv = [&](int kt) {
        uint32_t base = sb + AKV0 + (kt % 3) * AKVSTG;
        const __nv_bfloat16* srcs[4] = { ksh, ksl, vsh, vsl };
#pragma unroll
        for (int p = 0; p < 4; p++) {
#pragma unroll
            for (int i = 0; i < 2; i++) {
                int idx = tid + i*128;             // 0..255
                int r = idx >> 3, c = idx & 7;
                cp16(base + p*AKVPL + r*144 + c*16, srcs[p] + (size_t)(kt*32 + r)*64 + c*8);
            }
        }
        CP_COMMIT();
    };

    loadkv(0);
    loadkv(1);

    // ---- Q fragments (held whole kernel) ----
    CP_WAIT(2);
    __syncthreads();
    uint32_t QH[4][4], QL[4][4];
    {
        const uint32_t qro = (uint32_t)((w*16 + (lane & 15)) * 144 + ((lane >> 4) & 1) * 16);
#pragma unroll
        for (int kc = 0; kc < 4; kc++) {
            ldsm4(QH[kc], sb + 0*AQPL + qro + kc*32);
            ldsm4(QL[kc], sb + 1*AQPL + qro + kc*32);
        }
    }

    float o[8][4];
#pragma unroll
    for (int dn = 0; dn < 8; dn++)
#pragma unroll
        for (int j = 0; j < 4; j++) o[dn][j] = 0.f;
    float m0 = -1e30f, m1 = -1e30f, l0 = 0.f, l1 = 0.f;

    const uint32_t kro_base = (uint32_t)(((lane & 7) + ((lane >> 4) & 1) * 8) * 144
                                         + ((lane >> 3) & 1) * 16);
    const uint32_t vro_base = (uint32_t)(((lane & 7) + ((lane >> 3) & 1) * 8) * 144
                                         + ((lane >> 4) & 1) * 16);

    for (int kt = 0; kt < nkt; kt++) {
        if (kt + 1 < nkt) { CP_WAIT(1); } else { CP_WAIT(0); }
        __syncthreads();
        if (kt + 2 < nkt) loadkv(kt + 2);

        const int kt0 = kt * 32;
        if (kt0 > row_base + 15) continue;         // fully masked for this warp

        const uint32_t kvb = sb + AKV0 + (kt % 3) * AKVSTG;

        // ---- scores: 4 ntiles of 8 keys ----
        float acc[4][4];
#pragma unroll
        for (int nt = 0; nt < 4; nt++)
#pragma unroll
            for (int j = 0; j < 4; j++) acc[nt][j] = 0.f;

#pragma unroll
        for (int kk = 0; kk < 2; kk++) {
#pragma unroll
            for (int kc = 0; kc < 4; kc++) {
                uint32_t addr = kvb + kro_base + kk*16*144 + kc*32;
                uint32_t rh[4], rl[4];
                ldsm4(rh, addr);                   // Kh plane
                ldsm4(rl, addr + AKVPL);           // Kl plane
                mma16816(acc[kk*2+0], QH[kc], &rh[0]);
                mma16816(acc[kk*2+0], QL[kc], &rh[0]);
                mma16816(acc[kk*2+0], QH[kc], &rl[0]);
                mma16816(acc[kk*2+1], QH[kc], &rh[2]);
                mma16816(acc[kk*2+1], QL[kc], &rh[2]);
                mma16816(acc[kk*2+1], QH[kc], &rl[2]);
            }
        }

        // scale + causal mask
        const int row0 = row_base + gid, row1 = row0 + 8;
        const bool domask = (kt0 + 31 > row_base);
#pragma unroll
        for (int nt = 0; nt < 4; nt++) {
            int kcol = kt0 + nt*8 + tig*2;
#pragma unroll
            for (int j = 0; j < 4; j++) acc[nt][j] *= 0.125f;
            if (domask) {
                if (kcol     > row0) acc[nt][0] = -1e30f;
                if (kcol + 1 > row0) acc[nt][1] = -1e30f;
                if (kcol     > row1) acc[nt][2] = -1e30f;
                if (kcol + 1 > row1) acc[nt][3] = -1e30f;
            }
        }

        // ---- online softmax ----
        float mx0 = -1e30f, mx1 = -1e30f;
#pragma unroll
        for (int nt = 0; nt < 4; nt++) {
            mx0 = fmaxf(mx0, fmaxf(acc[nt][0], acc[nt][1]));
            mx1 = fmaxf(mx1, fmaxf(acc[nt][2], acc[nt][3]));
        }
        mx0 = fmaxf(mx0, __shfl_xor_sync(0xffffffffu, mx0, 1));
        mx0 = fmaxf(mx0, __shfl_xor_sync(0xffffffffu, mx0, 2));
        mx1 = fmaxf(mx1, __shfl_xor_sync(0xffffffffu, mx1, 1));
        mx1 = fmaxf(mx1, __shfl_xor_sync(0xffffffffu, mx1, 2));
        float m0n = fmaxf(m0, mx0), m1n = fmaxf(m1, mx1);
        float c0r = __expf(m0 - m0n), c1r = __expf(m1 - m1n);
        m0 = m0n; m1 = m1n;
        l0 *= c0r; l1 *= c1r;
#pragma unroll
        for (int dn = 0; dn < 8; dn++) {
            o[dn][0] *= c0r; o[dn][1] *= c0r;
            o[dn][2] *= c1r; o[dn][3] *= c1r;
        }
        float s0 = 0.f, s1 = 0.f;
#pragma unroll
        for (int nt = 0; nt < 4; nt++) {
            acc[nt][0] = __expf(acc[nt][0] - m0);
            acc[nt][1] = __expf(acc[nt][1] - m0);
            acc[nt][2] = __expf(acc[nt][2] - m1);
            acc[nt][3] = __expf(acc[nt][3] - m1);
            s0 += acc[nt][0] + acc[nt][1];
            s1 += acc[nt][2] + acc[nt][3];
        }
        s0 += __shfl_xor_sync(0xffffffffu, s0, 1);
        s0 += __shfl_xor_sync(0xffffffffu, s0, 2);
        s1 += __shfl_xor_sync(0xffffffffu, s1, 1);
        s1 += __shfl_xor_sync(0xffffffffu, s1, 2);
        l0 += s0; l1 += s1;

        // ---- P fragments (hi/lo) ----
        uint32_t PH[2][4], PL[2][4];
#pragma unroll
        for (int kk = 0; kk < 2; kk++) {
            float p00 = acc[2*kk][0],   p01 = acc[2*kk][1];
            float p02 = acc[2*kk][2],   p03 = acc[2*kk][3];
            float p10 = acc[2*kk+1][0], p11 = acc[2*kk+1][1];
            float p12 = acc[2*kk+1][2], p13 = acc[2*kk+1][3];
            PH[kk][0] = packb(p00, p01);
            PH[kk][1] = packb(p02, p03);
            PH[kk][2] = packb(p10, p11);
            PH[kk][3] = packb(p12, p13);
            PL[kk][0] = packb(p00 - __bfloat162float(__float2bfloat16(p00)),
                              p01 - __bfloat162float(__float2bfloat16(p01)));
            PL[kk][1] = packb(p02 - __bfloat162float(__float2bfloat16(p02)),
                              p03 - __bfloat162float(__float2bfloat16(p03)));
            PL[kk][2] = packb(p10 - __bfloat162float(__float2bfloat16(p10)),
                              p11 - __bfloat162float(__float2bfloat16(p11)));
            PL[kk][3] = packb(p12 - __bfloat162float(__float2bfloat16(p12)),
                              p13 - __bfloat162float(__float2bfloat16(p13)));
        }

        // ---- P x V ----
#pragma unroll
        for (int kk = 0; kk < 2; kk++) {
#pragma unroll
            for (int dc = 0; dc < 4; dc++) {
                uint32_t addr = kvb + 2*AKVPL + vro_base + kk*16*144 + dc*32;
                uint32_t vh4[4], vl4[4];
                ldsm4t(vh4, addr);                 // Vh plane
                ldsm4t(vl4, addr + AKVPL);         // Vl plane
                mma16816(o[dc*2+0], PH[kk], &vh4[0]);
                mma16816(o[dc*2+0], PL[kk], &vh4[0]);
                mma16816(o[dc*2+0], PH[kk], &vl4[0]);
                mma16816(o[dc*2+1], PH[kk], &vh4[2]);
                mma16816(o[dc*2+1], PL[kk], &vh4[2]);
                mma16816(o[dc*2+1], PH[kk], &vl4[2]);
            }
        }
    }

    // ---- epilogue ----
    const float i0 = 1.f / l0, i1 = 1.f / l1;
    const int grow0 = b*T_ + row_base + gid;
#pragma unroll
    for (int dn = 0; dn < 8; dn++) {
        int col = h*64 + dn*8 + tig*2;
        *(float2*)(g_y + (size_t)grow0 * D_ + col)       = make_float2(o[dn][0]*i0, o[dn][1]*i0);
        *(float2*)(g_y + (size_t)(grow0 + 8) * D_ + col) = make_float2(o[dn][2]*i1, o[dn][3]*i1);
    }
}

// ---------------- gated delta net scan v2: warp-synchronous, 8 lanes/col ----------------
__global__ void __launch_bounds__(128) gdn_kernel(const float* __restrict__ gv,
    const float* __restrict__ alpha, const float* __restrict__ beta,
    float* __restrict__ out)
{
    const int bh = blockIdx.x >> 3;
    const int cc = blockIdx.x & 7;
    const int b = bh >> 3, h = bh & 7;
    const int tid = threadIdx.x;
    const int col = cc*16 + (tid >> 3);
    const int e = tid & 7;                         // dims [e*8, e*8+8)

    float S[8];
#pragma unroll
    for (int i = 0; i < 8; i++) S[i] = 0.f;

    const float* kp = g_kn + ((size_t)b*T_*HG_ + h)*64 + e*8;
    const float* qp = g_qn + ((size_t)b*T_*HG_ + h)*64 + e*8;
    const float* vp = gv    + ((size_t)b*T_*HG_ + h)*128 + col;
    const float* ap = alpha + (size_t)b*T_*HG_ + h;
    const float* bp = beta  + (size_t)b*T_*HG_ + h;
    float* op = out + (size_t)b*T_*D_ + h*DV_ + col;

    float4 k0 = *(const float4*)kp,     k1 = *(const float4*)(kp+4);
    float4 q0 = *(const float4*)qp,     q1 = *(const float4*)(qp+4);
    float vt = *vp, av = *ap, bv = *bp;

    for (int t = 0; t < T_; ++t) {
        float4 nk0 = k0, nk1 = k1, nq0 = q0, nq1 = q1;
        float nv = vt, na = av, nb = bv;
        if (t + 1 < T_) {
            nk0 = *(const float4*)(kp + 512); nk1 = *(const float4*)(kp + 516);
            nq0 = *(const float4*)(qp + 512); nq1 = *(const float4*)(qp + 516);
            nv = vp[1024]; na = ap[8]; nb = bp[8];
        }

        float d0 = k0.x*S[0] + k0.y*S[1];
        float d1 = k0.z*S[2] + k0.w*S[3];
        float d2 = k1.x*S[4] + k1.y*S[5];
        float d3 = k1.z*S[6] + k1.w*S[7];
        float kS = (d0+d1) + (d2+d3);
        kS += __shfl_xor_sync(0xffffffffu, kS, 1);
        kS += __shfl_xor_sync(0xffffffffu, kS, 2);
        kS += __shfl_xor_sync(0xffffffffu, kS, 4);

        float coef = fmaf(-av*bv, kS, vt);
        S[0] = fmaf(coef, k0.x, av*S[0]);
        S[1] = fmaf(coef, k0.y, av*S[1]);
        S[2] = fmaf(coef, k0.z, av*S[2]);
        S[3] = fmaf(coef, k0.w, av*S[3]);
        S[4] = fmaf(coef, k1.x, av*S[4]);
        S[5] = fmaf(coef, k1.y, av*S[5]);
        S[6] = fmaf(coef, k1.z, av*S[6]);
        S[7] = fmaf(coef, k1.w, av*S[7]);

        float e0 = S[0]*q0.x + S[1]*q0.y;
        float e1 = S[2]*q0.z + S[3]*q0.w;
        float e2 = S[4]*q1.x + S[5]*q1.y;
        float e3 = S[6]*q1.z + S[7]*q1.w;
        float ov = (e0+e1) + (e2+e3);
        ov += __shfl_xor_sync(0xffffffffu, ov, 1);
        ov += __shfl_xor_sync(0xffffffffu, ov, 2);
        ov += __shfl_xor_sync(0xffffffffu, ov, 4);
        if (e == 0) op[0] += ov;

        kp += 512; qp += 512; vp += 1024; ap += 8; bp += 8; op += D_;
        k0 = nk0; k1 = nk1; q0 = nq0; q1 = nq1;
        vt = nv; av = na; bv = nb;
    }
}

// ---------------- launch ----------------
extern "C" void kernel_launch(void* const* d_in, const int* in_sizes, int n_in,
                              void* d_out, int out_size)
{
    const float* x     = (const float*)d_in[0];
    const float* Wq    = (const float*)d_in[1];
    const float* Wk    = (const float*)d_in[2];
    const float* Wv    = (const float*)d_in[3];
    const float* Wo    = (const float*)d_in[4];
    const float* qg    = (const float*)d_in[5];
    const float* gq    = (const float*)d_in[6];
    const float* gk    = (const float*)d_in[7];
    const float* gv    = (const float*)d_in[8];
    const float* alpha = (const float*)d_in[9];
    const float* beta  = (const float*)d_in[10];
    float* out = (float*)d_out;

    float *qkv,*yb,*qn,*kn;
    cudaGetSymbolAddress((void**)&qkv, g_qkv);
    cudaGetSymbolAddress((void**)&yb, g_y);
    cudaGetSymbolAddress((void**)&qn, g_qn);
    cudaGetSymbolAddress((void**)&kn, g_kn);

    __nv_bfloat16 *xh,*xl,*wh,*wl,*woh,*wol,*yh,*yl,*qbh,*qbl,*kbh,*kbl;
    cudaGetSymbolAddress((void**)&xh, g_xh);   cudaGetSymbolAddress((void**)&xl, g_xl);
    cudaGetSymbolAddress((void**)&wh, g_wh);   cudaGetSymbolAddress((void**)&wl, g_wl);
    cudaGetSymbolAddress((void**)&woh, g_woh); cudaGetSymbolAddress((void**)&wol, g_wol);
    cudaGetSymbolAddress((void**)&yh, g_yh);   cudaGetSymbolAddress((void**)&yl, g_yl);
    cudaGetSymbolAddress((void**)&qbh, g_qbh); cudaGetSymbolAddress((void**)&qbl, g_qbl);
    cudaGetSymbolAddress((void**)&kbh, g_kbh); cudaGetSymbolAddress((void**)&kbl, g_kbl);

    cudaFuncSetAttribute(gemm_mma, cudaFuncAttributeMaxDynamicSharedMemorySize, GEMM_SMEM);
    cudaFuncSetAttribute(attn_mma, cudaFuncAttributeMaxDynamicSharedMemorySize, ATT_SMEM);

    // 0-2: splits
    split_bf16<<<MT_*D_/4/256, 256>>>(x, xh, xl, MT_*D_/4);
    split_w_qkv<<<NQKV_*D_/4/256, 256>>>(Wq, Wk, Wv, wh, wl);
    split_bf16<<<D_*D_/4/256, 256>>>(Wo, woh, wol, D_*D_/4);

    // 3: fused QKV projection (ncu capture index)
    gemm_mma<<<dim3(NQKV_/128, MT_/128), 512, GEMM_SMEM>>>(xh, xl, wh, wl, qkv, MT_, NQKV_, D_);

    // norm/rope -> bf16 planes; V transpose -> bf16 planes
    rmsnorm_rope_bf16<<<(B_*T_*H_)/4, 128>>>(qkv, 0, qbh, qbl, qg, H_);
    rmsnorm_rope_bf16<<<(B_*T_*HKV_)/4, 128>>>(qkv, D_, kbh, kbl, (const float*)nullptr, HKV_);
    transpose_v_bf16<<<(B_*T_*HKV_*HD_)/256, 256>>>();

    // GDN input normalization
    l2norm64<<<(B_*T_*HG_)/4, 128>>>(gq, qn);
    l2norm64<<<(B_*T_*HG_)/4, 128>>>(gk, kn);

    // tensor-core causal attention -> g_y
    attn_mma<<<512, 128, ATT_SMEM>>>();

    // output projection -> d_out
    split_bf16<<<MT_*D_/4/256, 256>>>(yb, yh, yl, MT_*D_/4);
    gemm_mma<<<dim3(D_/128, MT_/128), 512, GEMM_SMEM>>>(yh, yl, woh, wol, out, MT_, D_, D_);

    // GDN scan accumulates into d_out
    gdn_kernel<<<128, 128>>>(gv, alpha, beta, out);
}

// round 7
// speedup vs baseline: 1.5340x; 1.0196x over previous
#include <cuda_runtime.h>
#include <cuda_bf16.h>
#include <cstdint>

// ---------------- problem constants ----------------
static constexpr int B_  = 2;
static constexpr int T_  = 1024;
static constexpr int D_  = 1024;
static constexpr int H_  = 16;
static constexpr int HKV_ = 4;
static constexpr int HD_ = 64;
static constexpr int HG_ = 8;
static constexpr int DV_ = 128;

static constexpr int MT_ = B_*T_;               // 2048 rows
static constexpr int NQKV_ = D_ + 2*HKV_*HD_;   // 1536

// ---------------- scratch ----------------
__device__ float g_qkv[MT_*NQKV_];
__device__ float g_qn[B_*T_*HG_*64];
__device__ float g_kn[B_*T_*HG_*64];

// bf16 attention operand planes, layout (b,h,t,d)
__device__ __nv_bfloat16 g_qbh[B_*H_*T_*HD_],  g_qbl[B_*H_*T_*HD_];
__device__ __nv_bfloat16 g_kbh[B_*HKV_*T_*HD_], g_kbl[B_*HKV_*T_*HD_];
__device__ __nv_bfloat16 g_vbh[B_*HKV_*T_*HD_], g_vbl[B_*HKV_*T_*HD_];

// bf16 GEMM planes
__device__ __nv_bfloat16 g_xh[MT_*D_],  g_xl[MT_*D_];
__device__ __nv_bfloat16 g_wh[NQKV_*D_], g_wl[NQKV_*D_];
__device__ __nv_bfloat16 g_woh[D_*D_],  g_wol[D_*D_];
__device__ __nv_bfloat16 g_yh[MT_*D_],  g_yl[MT_*D_];   // attention output planes

// ---------------- PTX helpers ----------------
__device__ __forceinline__ uint32_t smem_u32(const void* p) {
    uint32_t a;
    asm("{ .reg .u64 t; cvta.to.shared.u64 t, %1; cvt.u32.u64 %0, t; }" : "=r"(a) : "l"(p));
    return a;
}
__device__ __forceinline__ void ldsm4(uint32_t (&r)[4], uint32_t addr) {
    asm volatile("ldmatrix.sync.aligned.m8n8.x4.shared.b16 {%0,%1,%2,%3}, [%4];"
        : "=r"(r[0]), "=r"(r[1]), "=r"(r[2]), "=r"(r[3]) : "r"(addr));
}
__device__ __forceinline__ void ldsm4t(uint32_t (&r)[4], uint32_t addr) {
    asm volatile("ldmatrix.sync.aligned.m8n8.x4.trans.shared.b16 {%0,%1,%2,%3}, [%4];"
        : "=r"(r[0]), "=r"(r[1]), "=r"(r[2]), "=r"(r[3]) : "r"(addr));
}
__device__ __forceinline__ void mma16816(float (&d)[4], const uint32_t (&a)[4],
                                         const uint32_t* b) {
    asm volatile("mma.sync.aligned.m16n8k16.row.col.f32.bf16.bf16.f32 "
        "{%0,%1,%2,%3}, {%4,%5,%6,%7}, {%8,%9}, {%0,%1,%2,%3};"
        : "+f"(d[0]), "+f"(d[1]), "+f"(d[2]), "+f"(d[3])
        : "r"(a[0]), "r"(a[1]), "r"(a[2]), "r"(a[3]), "r"(b[0]), "r"(b[1]));
}
__device__ __forceinline__ void cp16(uint32_t saddr, const void* gaddr) {
    asm volatile("cp.async.cg.shared.global [%0], [%1], 16;" :: "r"(saddr), "l"(gaddr));
}
#define CP_COMMIT() asm volatile("cp.async.commit_group;" ::: "memory")
#define CP_WAIT(n)  asm volatile("cp.async.wait_group %0;" :: "n"(n) : "memory")

__device__ __forceinline__ uint32_t packb(float x, float y) {
    __nv_bfloat162 t(__float2bfloat16(x), __float2bfloat16(y));
    return *(uint32_t*)&t;
}

// ---------------- fp32 -> bf16 hi/lo split ----------------
__device__ __forceinline__ void split4(float4 v, __nv_bfloat16* hi, __nv_bfloat16* lo, int i)
{
    __nv_bfloat16 h0 = __float2bfloat16(v.x), h1 = __float2bfloat16(v.y);
    __nv_bfloat16 h2 = __float2bfloat16(v.z), h3 = __float2bfloat16(v.w);
    __nv_bfloat16 l0 = __float2bfloat16(v.x - __bfloat162float(h0));
    __nv_bfloat16 l1 = __float2bfloat16(v.y - __bfloat162float(h1));
    __nv_bfloat16 l2 = __float2bfloat16(v.z - __bfloat162float(h2));
    __nv_bfloat16 l3 = __float2bfloat16(v.w - __bfloat162float(h3));
    ((__nv_bfloat162*)hi)[2*i]   = __nv_bfloat162(h0, h1);
    ((__nv_bfloat162*)hi)[2*i+1] = __nv_bfloat162(h2, h3);
    ((__nv_bfloat162*)lo)[2*i]   = __nv_bfloat162(l0, l1);
    ((__nv_bfloat162*)lo)[2*i+1] = __nv_bfloat162(l2, l3);
}

__global__ void split_bf16(const float* __restrict__ src,
                           __nv_bfloat16* __restrict__ hi,
                           __nv_bfloat16* __restrict__ lo, int n4)
{
    int i = blockIdx.x * 256 + threadIdx.x;
    if (i >= n4) return;
    split4(((const float4*)src)[i], hi, lo, i);
}

__global__ void split_w_qkv(const float* __restrict__ Wq, const float* __restrict__ Wk,
                            const float* __restrict__ Wv,
                            __nv_bfloat16* __restrict__ hi, __nv_bfloat16* __restrict__ lo)
{
    int i = blockIdx.x * 256 + threadIdx.x;
    int e = i * 4;
    int row = e >> 10, col = e & 1023;
    const float* src;
    if (row < D_)               src = Wq + (size_t)row * D_ + col;
    else if (row < D_ + 256)    src = Wk + (size_t)(row - D_) * D_ + col;
    else                        src = Wv + (size_t)(row - D_ - 256) * D_ + col;
    split4(*(const float4*)src, hi, lo, i);
}

// ---------------- mma.sync bf16x2-split GEMM (pass-major MMA order) ----------------
static constexpr int ROWSTRIDE = 40;
static constexpr int PLANE_B = 128 * ROWSTRIDE * 2;
static constexpr int STAGE_B = 4 * PLANE_B;
static constexpr int NSTAGE  = 3;
static constexpr int GEMM_SMEM = NSTAGE * STAGE_B;

__global__ void __launch_bounds__(512) gemm_mma(
    const __nv_bfloat16* __restrict__ Ah, const __nv_bfloat16* __restrict__ Al,
    const __nv_bfloat16* __restrict__ Bh, const __nv_bfloat16* __restrict__ Bl,
    float* __restrict__ C, int M, int N, int K)
{
    extern __shared__ __align__(128) char smem[];
    const uint32_t sb = smem_u32(smem);
    const int tid = threadIdx.x;
    const int wid = tid >> 5, lane = tid & 31;
    const int wr = wid & 3, wc = wid >> 2;
    const int m0 = blockIdx.y * 128;
    const int n0 = blockIdx.x * 128;
    const int NC = K >> 5;

    const int lrow = tid >> 2, lc16 = tid & 3;
    const uint32_t soff = (uint32_t)(lrow * (ROWSTRIDE*2) + lc16 * 16);
    const size_t gaoff = (size_t)(m0 + lrow) * K + lc16 * 8;
    const size_t gboff = (size_t)(n0 + lrow) * K + lc16 * 8;

    auto issue = [&](int kc) {
        uint32_t sd = sb + (kc % NSTAGE) * STAGE_B + soff;
        const int ko = kc * 32;
        cp16(sd + 0*PLANE_B, Ah + gaoff + ko);
        cp16(sd + 1*PLANE_B, Al + gaoff + ko);
        cp16(sd + 2*PLANE_B, Bh + gboff + ko);
        cp16(sd + 3*PLANE_B, Bl + gboff + ko);
        CP_COMMIT();
    };

    float acc[2][4][4];
#pragma unroll
    for (int mt = 0; mt < 2; mt++)
#pragma unroll
        for (int nt = 0; nt < 4; nt++)
#pragma unroll
            for (int j = 0; j < 4; j++) acc[mt][nt][j] = 0.f;

    issue(0);
    if (NC > 1) issue(1);

    const int lr = lane & 15, lchi = lane >> 4;

    for (int c = 0; c < NC; c++) {
        if (c + 1 < NC) { CP_WAIT(1); } else { CP_WAIT(0); }
        __syncthreads();
        if (c + 2 < NC) issue(c + 2);
        const uint32_t st = sb + (c % NSTAGE) * STAGE_B;
#pragma unroll
        for (int ks = 0; ks < 2; ks++) {
            const int koff = ks * 16 + lchi * 8;
            uint32_t aH[2][4], aL[2][4], bH[4][2], bL[4][2];
#pragma unroll
            for (int mt = 0; mt < 2; mt++) {
                uint32_t ro = (uint32_t)(((wr*32 + mt*16 + lr) * ROWSTRIDE + koff) * 2);
                ldsm4(aH[mt], st + 0*PLANE_B + ro);
                ldsm4(aL[mt], st + 1*PLANE_B + ro);
            }
#pragma unroll
            for (int np = 0; np < 2; np++) {
                uint32_t ro = (uint32_t)(((wc*32 + np*16 + lr) * ROWSTRIDE + koff) * 2);
                uint32_t t[4];
                ldsm4(t, st + 2*PLANE_B + ro);
                bH[np*2+0][0] = t[0]; bH[np*2+0][1] = t[2];
                bH[np*2+1][0] = t[1]; bH[np*2+1][1] = t[3];
                ldsm4(t, st + 3*PLANE_B + ro);
                bL[np*2+0][0] = t[0]; bL[np*2+0][1] = t[2];
                bL[np*2+1][0] = t[1]; bL[np*2+1][1] = t[3];
            }
            // pass-major: 8 independent accumulators per pass
#pragma unroll
            for (int mt = 0; mt < 2; mt++)
#pragma unroll
                for (int nt = 0; nt < 4; nt++)
                    mma16816(acc[mt][nt], aH[mt], bH[nt]);
#pragma unroll
            for (int mt = 0; mt < 2; mt++)
#pragma unroll
                for (int nt = 0; nt < 4; nt++)
                    mma16816(acc[mt][nt], aL[mt], bH[nt]);
#pragma unroll
            for (int mt = 0; mt < 2; mt++)
#pragma unroll
                for (int nt = 0; nt < 4; nt++)
                    mma16816(acc[mt][nt], aH[mt], bL[nt]);
        }
        __syncthreads();
    }

    const int er = m0 + wr*32 + (lane >> 2);
    const int ec = n0 + wc*32 + (lane & 3) * 2;
#pragma unroll
    for (int mt = 0; mt < 2; mt++)
#pragma unroll
        for (int nt = 0; nt < 4; nt++) {
            float* p0 = C + (size_t)(er + mt*16) * N + ec + nt*8;
            float* p1 = C + (size_t)(er + mt*16 + 8) * N + ec + nt*8;
            *(float2*)p0 = make_float2(acc[mt][nt][0], acc[mt][nt][1]);
            *(float2*)p1 = make_float2(acc[mt][nt][2], acc[mt][nt][3]);
        }
}

// ---------------- RMSNorm + RoPE -> bf16 hi/lo planes (b,h,t,d) ----------------
__global__ void rmsnorm_rope_bf16(const float* __restrict__ src, int colofs,
                                  __nv_bfloat16* __restrict__ dsth,
                                  __nv_bfloat16* __restrict__ dstl,
                                  const float* __restrict__ gain, int nheads)
{
    int warp = threadIdx.x >> 5, lane = threadIdx.x & 31;
    int item = blockIdx.x*4 + warp;
    int h = item % nheads;
    int row = item / nheads;
    int tpos = row & (T_-1);
    int b = row >> 10;
    const float* p = src + (size_t)row * NQKV_ + colofs + h*64;
    float x1 = p[lane], x2 = p[lane+32];
    float ss = x1*x1 + x2*x2;
#pragma unroll
    for (int o = 16; o > 0; o >>= 1) ss += __shfl_xor_sync(0xffffffffu, ss, o);
    float r = rsqrtf(ss*(1.0f/64.0f) + 1e-6f);
    x1 *= r; x2 *= r;
    float invf = expf(-(float)lane * (9.210340371976184f/32.0f));
    float ang = (float)tpos * invf;
    float sv, cv;
    sincosf(ang, &sv, &cv);
    float g = gain ? gain[h] : 1.0f;
    float o1 = (x1*cv + x2*sv) * g;
    float o2 = (x2*cv - x1*sv) * g;
    size_t base = (((size_t)(b*nheads + h)*T_) + tpos)*64;
    __nv_bfloat16 h1 = __float2bfloat16(o1), h2 = __float2bfloat16(o2);
    dsth[base + lane]      = h1;
    dsth[base + lane + 32] = h2;
    dstl[base + lane]      = __float2bfloat16(o1 - __bfloat162float(h1));
    dstl[base + lane + 32] = __float2bfloat16(o2 - __bfloat162float(h2));
}

// ---------------- V transpose -> bf16 hi/lo (b,h,t,d) ----------------
__global__ void transpose_v_bf16()
{
    int idx = blockIdx.x*256 + threadIdx.x;
    int d = idx & 63;
    int h = (idx >> 6) & 3;
    int t = (idx >> 8) & 1023;
    int b = idx >> 18;
    int row = b*T_ + t;
    float v = g_qkv[(size_t)row * NQKV_ + (D_ + 256) + h*64 + d];
    size_t o = (((size_t)(b*HKV_ + h))*T_ + t)*64 + d;
    __nv_bfloat16 hv = __float2bfloat16(v);
    g_vbh[o] = hv;
    g_vbl[o] = __float2bfloat16(v - __bfloat162float(hv));
}

__global__ void l2norm64(const float* __restrict__ src, float* __restrict__ dst)
{
    int warp = threadIdx.x >> 5, lane = threadIdx.x & 31;
    int item = blockIdx.x*4 + warp;
    const float* p = src + (size_t)item*64;
    float x1 = p[lane], x2 = p[lane+32];
    float ss = x1*x1 + x2*x2;
#pragma unroll
    for (int o = 16; o > 0; o >>= 1) ss += __shfl_xor_sync(0xffffffffu, ss, o);
    float n = sqrtf(ss);
    float r = 1.0f / fmaxf(n, 1e-6f);
    dst[(size_t)item*64 + lane]      = x1*r;
    dst[(size_t)item*64 + lane + 32] = x2*r;
}

// ---------------- flash attention on mma.sync (pass-major, bf16 epilogue) ----------------
static constexpr int ASTRIDE = 72;
static constexpr int AQPL = 64 * ASTRIDE * 2;      // 9216
static constexpr int AKV0 = 2 * AQPL;              // 18432
static constexpr int AKVPL = 32 * ASTRIDE * 2;     // 4608
static constexpr int AKVSTG = 4 * AKVPL;           // 18432
static constexpr int ATT_SMEM = AKV0 + 3 * AKVSTG; // 73728

__global__ void __launch_bounds__(128, 1) attn_mma()
{
    extern __shared__ __align__(128) char sm[];
    const uint32_t sb = smem_u32(sm);
    const int bx = blockIdx.x;
    const int qt = 15 - (bx >> 5);
    const int bh = bx & 31;
    const int b = bh >> 4, h = bh & 15;
    const int tid = threadIdx.x, w = tid >> 5, lane = tid & 31;
    const int gid = lane >> 2, tig = lane & 3;
    const int nkt = 2 * (qt + 1);
    const int row_base = qt*64 + w*16;

    const __nv_bfloat16* qsh = g_qbh + (((size_t)(b*H_ + h)*T_) + qt*64)*64;
    const __nv_bfloat16* qsl = g_qbl + (((size_t)(b*H_ + h)*T_) + qt*64)*64;
    const __nv_bfloat16* ksh = g_kbh + ((size_t)(b*HKV_ + (h>>2))*T_)*64;
    const __nv_bfloat16* ksl = g_kbl + ((size_t)(b*HKV_ + (h>>2))*T_)*64;
    const __nv_bfloat16* vsh = g_vbh + ((size_t)(b*HKV_ + (h>>2))*T_)*64;
    const __nv_bfloat16* vsl = g_vbl + ((size_t)(b*HKV_ + (h>>2))*T_)*64;

#pragma unroll
    for (int i = 0; i < 8; i++) {
        int idx = tid + i*128;
        int plane = idx >> 9, rem = idx & 511;
        int r = rem >> 3, c = rem & 7;
        const __nv_bfloat16* src = plane ? qsl : qsh;
        cp16(sb + plane*AQPL + r*144 + c*16, src + r*64 + c*8);
    }
    CP_COMMIT();

    auto loadkv = [&](int kt) {
        uint32_t base = sb + AKV0 + (kt % 3) * AKVSTG;
        const __nv_bfloat16* srcs[4] = { ksh, ksl, vsh, vsl };
#pragma unroll
        for (int p = 0; p < 4; p++) {
#pragma unroll
            for (int i = 0; i < 2; i++) {
                int idx = tid + i*128;
                int r = idx >> 3, c = idx & 7;
                cp16(base + p*AKVPL + r*144 + c*16, srcs[p] + (size_t)(kt*32 + r)*64 + c*8);
            }
        }
        CP_COMMIT();
    };

    loadkv(0);
    loadkv(1);

    CP_WAIT(2);
    __syncthreads();
    uint32_t QH[4][4], QL[4][4];
    {
        const uint32_t qro = (uint32_t)((w*16 + (lane & 15)) * 144 + ((lane >> 4) & 1) * 16);
#pragma unroll
        for (int kc = 0; kc < 4; kc++) {
            ldsm4(QH[kc], sb + 0*AQPL + qro + kc*32);
            ldsm4(QL[kc], sb + 1*AQPL + qro + kc*32);
        }
    }

    float o[8][4];
#pragma unroll
    for (int dn = 0; dn < 8; dn++)
#pragma unroll
        for (int j = 0; j < 4; j++) o[dn][j] = 0.f;
    float m0 = -1e30f, m1 = -1e30f, l0 = 0.f, l1 = 0.f;

    const uint32_t kro_base = (uint32_t)(((lane & 7) + ((lane >> 4) & 1) * 8) * 144
                                         + ((lane >> 3) & 1) * 16);
    const uint32_t vro_base = (uint32_t)(((lane & 7) + ((lane >> 3) & 1) * 8) * 144
                                         + ((lane >> 4) & 1) * 16);

    for (int kt = 0; kt < nkt; kt++) {
        if (kt + 1 < nkt) { CP_WAIT(1); } else { CP_WAIT(0); }
        __syncthreads();
        if (kt + 2 < nkt) loadkv(kt + 2);

        const int kt0 = kt * 32;
        if (kt0 > row_base + 15) continue;

        const uint32_t kvb = sb + AKV0 + (kt % 3) * AKVSTG;

        // ---- scores: pass-major, 4 independent accs ----
        float acc[4][4];
#pragma unroll
        for (int nt = 0; nt < 4; nt++)
#pragma unroll
            for (int j = 0; j < 4; j++) acc[nt][j] = 0.f;

#pragma unroll
        for (int kc = 0; kc < 4; kc++) {
            uint32_t a0 = kvb + kro_base + kc*32;            // keys 0-15 (kk=0)
            uint32_t a1 = a0 + 16*144;                       // keys 16-31 (kk=1)
            uint32_t h0[4], l0f[4], h1[4], l1f[4];
            ldsm4(h0, a0);
            ldsm4(l0f, a0 + AKVPL);
            ldsm4(h1, a1);
            ldsm4(l1f, a1 + AKVPL);
            mma16816(acc[0], QH[kc], &h0[0]);
            mma16816(acc[1], QH[kc], &h0[2]);
            mma16816(acc[2], QH[kc], &h1[0]);
            mma16816(acc[3], QH[kc], &h1[2]);
            mma16816(acc[0], QL[kc], &h0[0]);
            mma16816(acc[1], QL[kc], &h0[2]);
            mma16816(acc[2], QL[kc], &h1[0]);
            mma16816(acc[3], QL[kc], &h1[2]);
            mma16816(acc[0], QH[kc], &l0f[0]);
            mma16816(acc[1], QH[kc], &l0f[2]);
            mma16816(acc[2], QH[kc], &l1f[0]);
            mma16816(acc[3], QH[kc], &l1f[2]);
        }

        // scale + causal mask
        const int row0 = row_base + gid, row1 = row0 + 8;
        const bool domask = (kt0 + 31 > row_base);
#pragma unroll
        for (int nt = 0; nt < 4; nt++) {
            int kcol = kt0 + nt*8 + tig*2;
#pragma unroll
            for (int j = 0; j < 4; j++) acc[nt][j] *= 0.125f;
            if (domask) {
                if (kcol     > row0) acc[nt][0] = -1e30f;
                if (kcol + 1 > row0) acc[nt][1] = -1e30f;
                if (kcol     > row1) acc[nt][2] = -1e30f;
                if (kcol + 1 > row1) acc[nt][3] = -1e30f;
            }
        }

        // ---- online softmax ----
        float mx0 = -1e30f, mx1 = -1e30f;
#pragma unroll
        for (int nt = 0; nt < 4; nt++) {
            mx0 = fmaxf(mx0, fmaxf(acc[nt][0], acc[nt][1]));
            mx1 = fmaxf(mx1, fmaxf(acc[nt][2], acc[nt][3]));
        }
        mx0 = fmaxf(mx0, __shfl_xor_sync(0xffffffffu, mx0, 1));
        mx0 = fmaxf(mx0, __shfl_xor_sync(0xffffffffu, mx0, 2));
        mx1 = fmaxf(mx1, __shfl_xor_sync(0xffffffffu, mx1, 1));
        mx1 = fmaxf(mx1, __shfl_xor_sync(0xffffffffu, mx1, 2));
        float m0n = fmaxf(m0, mx0), m1n = fmaxf(m1, mx1);
        float c0r = __expf(m0 - m0n), c1r = __expf(m1 - m1n);
        m0 = m0n; m1 = m1n;
        l0 *= c0r; l1 *= c1r;
#pragma unroll
        for (int dn = 0; dn < 8; dn++) {
            o[dn][0] *= c0r; o[dn][1] *= c0r;
            o[dn][2] *= c1r; o[dn][3] *= c1r;
        }
        float s0 = 0.f, s1 = 0.f;
#pragma unroll
        for (int nt = 0; nt < 4; nt++) {
            acc[nt][0] = __expf(acc[nt][0] - m0);
            acc[nt][1] = __expf(acc[nt][1] - m0);
            acc[nt][2] = __expf(acc[nt][2] - m1);
            acc[nt][3] = __expf(acc[nt][3] - m1);
            s0 += acc[nt][0] + acc[nt][1];
            s1 += acc[nt][2] + acc[nt][3];
        }
        s0 += __shfl_xor_sync(0xffffffffu, s0, 1);
        s0 += __shfl_xor_sync(0xffffffffu, s0, 2);
        s1 += __shfl_xor_sync(0xffffffffu, s1, 1);
        s1 += __shfl_xor_sync(0xffffffffu, s1, 2);
        l0 += s0; l1 += s1;

        // ---- P fragments (hi/lo) ----
        uint32_t PH[2][4], PL[2][4];
#pragma unroll
        for (int kk = 0; kk < 2; kk++) {
            float p00 = acc[2*kk][0],   p01 = acc[2*kk][1];
            float p02 = acc[2*kk][2],   p03 = acc[2*kk][3];
            float p10 = acc[2*kk+1][0], p11 = acc[2*kk+1][1];
            float p12 = acc[2*kk+1][2], p13 = acc[2*kk+1][3];
            PH[kk][0] = packb(p00, p01);
            PH[kk][1] = packb(p02, p03);
            PH[kk][2] = packb(p10, p11);
            PH[kk][3] = packb(p12, p13);
            PL[kk][0] = packb(p00 - __bfloat162float(__float2bfloat16(p00)),
                              p01 - __bfloat162float(__float2bfloat16(p01)));
            PL[kk][1] = packb(p02 - __bfloat162float(__float2bfloat16(p02)),
                              p03 - __bfloat162float(__float2bfloat16(p03)));
            PL[kk][2] = packb(p10 - __bfloat162float(__float2bfloat16(p10)),
                              p11 - __bfloat162float(__float2bfloat16(p11)));
            PL[kk][3] = packb(p12 - __bfloat162float(__float2bfloat16(p12)),
                              p13 - __bfloat162float(__float2bfloat16(p13)));
        }

        // ---- P x V: pass-major over dc pairs (4 independent accs/pass) ----
#pragma unroll
        for (int kk = 0; kk < 2; kk++) {
#pragma unroll
            for (int dcp = 0; dcp < 2; dcp++) {
                uint32_t aA = kvb + 2*AKVPL + vro_base + kk*16*144 + (dcp*2)*32;
                uint32_t aB = aA + 32;
                uint32_t vhA[4], vlA[4], vhB[4], vlB[4];
                ldsm4t(vhA, aA);
                ldsm4t(vlA, aA + AKVPL);
                ldsm4t(vhB, aB);
                ldsm4t(vlB, aB + AKVPL);
                float (&oA0)[4] = o[dcp*4+0];
                float (&oA1)[4] = o[dcp*4+1];
                float (&oB0)[4] = o[dcp*4+2];
                float (&oB1)[4] = o[dcp*4+3];
                mma16816(oA0, PH[kk], &vhA[0]);
                mma16816(oA1, PH[kk], &vhA[2]);
                mma16816(oB0, PH[kk], &vhB[0]);
                mma16816(oB1, PH[kk], &vhB[2]);
                mma16816(oA0, PL[kk], &vhA[0]);
                mma16816(oA1, PL[kk], &vhA[2]);
                mma16816(oB0, PL[kk], &vhB[0]);
                mma16816(oB1, PL[kk], &vhB[2]);
                mma16816(oA0, PH[kk], &vlA[0]);
                mma16816(oA1, PH[kk], &vlA[2]);
                mma16816(oB0, PH[kk], &vlB[0]);
                mma16816(oB1, PH[kk], &vlB[2]);
            }
        }
    }

    // ---- epilogue: emit bf16 hi/lo planes directly (Wo GEMM input) ----
    const float i0 = 1.f / l0, i1 = 1.f / l1;
    const int grow0 = b*T_ + row_base + gid;
#pragma unroll
    for (int dn = 0; dn < 8; dn++) {
        // NOTE: o index mapping — dn = dcp*4 + {0,1,2,3} covers dim cols:
        // dcp*2*16 + {0..7 (A0), 8..15 (A1), 16..23 (B0), 24..31 (B1)}
        int dcp = dn >> 2, sub = dn & 3;
        int col = h*64 + dcp*32 + sub*8 + tig*2;
        float a0 = o[dn][0]*i0, a1 = o[dn][1]*i0;
        float a2 = o[dn][2]*i1, a3 = o[dn][3]*i1;
        __nv_bfloat16 h0 = __float2bfloat16(a0), h1 = __float2bfloat16(a1);
        __nv_bfloat16 h2 = __float2bfloat16(a2), h3 = __float2bfloat16(a3);
        size_t p0 = (size_t)grow0 * D_ + col;
        size_t p1 = (size_t)(grow0 + 8) * D_ + col;
        *(__nv_bfloat162*)(g_yh + p0) = __nv_bfloat162(h0, h1);
        *(__nv_bfloat162*)(g_yh + p1) = __nv_bfloat162(h2, h3);
        *(__nv_bfloat162*)(g_yl + p0) = __nv_bfloat162(
            __float2bfloat16(a0 - __bfloat162float(h0)),
            __float2bfloat16(a1 - __bfloat162float(h1)));
        *(__nv_bfloat162*)(g_yl + p1) = __nv_bfloat162(
            __float2bfloat16(a2 - __bfloat162float(h2)),
            __float2bfloat16(a3 - __bfloat162float(h3)));
    }
}

// ---------------- gated delta net scan (warp-synchronous, unchanged) ----------------
__global__ void __launch_bounds__(128) gdn_kernel(const float* __restrict__ gv,
    const float* __restrict__ alpha, const float* __restrict__ beta,
    float* __restrict__ out)
{
    const int bh = blockIdx.x >> 3;
    const int cc = blockIdx.x & 7;
    const int b = bh >> 3, h = bh & 7;
    const int tid = threadIdx.x;
    const int col = cc*16 + (tid >> 3);
    const int e = tid & 7;

    float S[8];
#pragma unroll
    for (int i = 0; i < 8; i++) S[i] = 0.f;

    const float* kp = g_kn + ((size_t)b*T_*HG_ + h)*64 + e*8;
    const float* qp = g_qn + ((size_t)b*T_*HG_ + h)*64 + e*8;
    const float* vp = gv    + ((size_t)b*T_*HG_ + h)*128 + col;
    const float* ap = alpha + (size_t)b*T_*HG_ + h;
    const float* bp = beta  + (size_t)b*T_*HG_ + h;
    float* op = out + (size_t)b*T_*D_ + h*DV_ + col;

    float4 k0 = *(const float4*)kp,     k1 = *(const float4*)(kp+4);
    float4 q0 = *(const float4*)qp,     q1 = *(const float4*)(qp+4);
    float vt = *vp, av = *ap, bv = *bp;

    for (int t = 0; t < T_; ++t) {
        float4 nk0 = k0, nk1 = k1, nq0 = q0, nq1 = q1;
        float nv = vt, na = av, nb = bv;
        if (t + 1 < T_) {
            nk0 = *(const float4*)(kp + 512); nk1 = *(const float4*)(kp + 516);
            nq0 = *(const float4*)(qp + 512); nq1 = *(const float4*)(qp + 516);
            nv = vp[1024]; na = ap[8]; nb = bp[8];
        }

        float d0 = k0.x*S[0] + k0.y*S[1];
        float d1 = k0.z*S[2] + k0.w*S[3];
        float d2 = k1.x*S[4] + k1.y*S[5];
        float d3 = k1.z*S[6] + k1.w*S[7];
        float kS = (d0+d1) + (d2+d3);
        kS += __shfl_xor_sync(0xffffffffu, kS, 1);
        kS += __shfl_xor_sync(0xffffffffu, kS, 2);
        kS += __shfl_xor_sync(0xffffffffu, kS, 4);

        float coef = fmaf(-av*bv, kS, vt);
        S[0] = fmaf(coef, k0.x, av*S[0]);
        S[1] = fmaf(coef, k0.y, av*S[1]);
        S[2] = fmaf(coef, k0.z, av*S[2]);
        S[3] = fmaf(coef, k0.w, av*S[3]);
        S[4] = fmaf(coef, k1.x, av*S[4]);
        S[5] = fmaf(coef, k1.y, av*S[5]);
        S[6] = fmaf(coef, k1.z, av*S[6]);
        S[7] = fmaf(coef, k1.w, av*S[7]);

        float e0 = S[0]*q0.x + S[1]*q0.y;
        float e1 = S[2]*q0.z + S[3]*q0.w;
        float e2 = S[4]*q1.x + S[5]*q1.y;
        float e3 = S[6]*q1.z + S[7]*q1.w;
        float ov = (e0+e1) + (e2+e3);
        ov += __shfl_xor_sync(0xffffffffu, ov, 1);
        ov += __shfl_xor_sync(0xffffffffu, ov, 2);
        ov += __shfl_xor_sync(0xffffffffu, ov, 4);
        if (e == 0) op[0] += ov;

        kp += 512; qp += 512; vp += 1024; ap += 8; bp += 8; op += D_;
        k0 = nk0; k1 = nk1; q0 = nq0; q1 = nq1;
        vt = nv; av = na; bv = nb;
    }
}

// ---------------- launch ----------------
extern "C" void kernel_launch(void* const* d_in, const int* in_sizes, int n_in,
                              void* d_out, int out_size)
{
    const float* x     = (const float*)d_in[0];
    const float* Wq    = (const float*)d_in[1];
    const float* Wk    = (const float*)d_in[2];
    const float* Wv    = (const float*)d_in[3];
    const float* Wo    = (const float*)d_in[4];
    const float* qg    = (const float*)d_in[5];
    const float* gq    = (const float*)d_in[6];
    const float* gk    = (const float*)d_in[7];
    const float* gv    = (const float*)d_in[8];
    const float* alpha = (const float*)d_in[9];
    const float* beta  = (const float*)d_in[10];
    float* out = (float*)d_out;

    float *qkv,*qn,*kn;
    cudaGetSymbolAddress((void**)&qkv, g_qkv);
    cudaGetSymbolAddress((void**)&qn, g_qn);
    cudaGetSymbolAddress((void**)&kn, g_kn);

    __nv_bfloat16 *xh,*xl,*wh,*wl,*woh,*wol,*yh,*yl,*qbh,*qbl,*kbh,*kbl;
    cudaGetSymbolAddress((void**)&xh, g_xh);   cudaGetSymbolAddress((void**)&xl, g_xl);
    cudaGetSymbolAddress((void**)&wh, g_wh);   cudaGetSymbolAddress((void**)&wl, g_wl);
    cudaGetSymbolAddress((void**)&woh, g_woh); cudaGetSymbolAddress((void**)&wol, g_wol);
    cudaGetSymbolAddress((void**)&yh, g_yh);   cudaGetSymbolAddress((void**)&yl, g_yl);
    cudaGetSymbolAddress((void**)&qbh, g_qbh); cudaGetSymbolAddress((void**)&qbl, g_qbl);
    cudaGetSymbolAddress((void**)&kbh, g_kbh); cudaGetSymbolAddress((void**)&kbl, g_kbl);

    cudaFuncSetAttribute(gemm_mma, cudaFuncAttributeMaxDynamicSharedMemorySize, GEMM_SMEM);
    cudaFuncSetAttribute(attn_mma, cudaFuncAttributeMaxDynamicSharedMemorySize, ATT_SMEM);

    // 0-2: splits
    split_bf16<<<MT_*D_/4/256, 256>>>(x, xh, xl, MT_*D_/4);
    split_w_qkv<<<NQKV_*D_/4/256, 256>>>(Wq, Wk, Wv, wh, wl);
    split_bf16<<<D_*D_/4/256, 256>>>(Wo, woh, wol, D_*D_/4);

    // 3: fused QKV projection (ncu capture index)
    gemm_mma<<<dim3(NQKV_/128, MT_/128), 512, GEMM_SMEM>>>(xh, xl, wh, wl, qkv, MT_, NQKV_, D_);

    // norm/rope -> bf16 planes; V transpose -> bf16 planes
    rmsnorm_rope_bf16<<<(B_*T_*H_)/4, 128>>>(qkv, 0, qbh, qbl, qg, H_);
    rmsnorm_rope_bf16<<<(B_*T_*HKV_)/4, 128>>>(qkv, D_, kbh, kbl, (const float*)nullptr, HKV_);
    transpose_v_bf16<<<(B_*T_*HKV_*HD_)/256, 256>>>();

    // GDN input normalization
    l2norm64<<<(B_*T_*HG_)/4, 128>>>(gq, qn);
    l2norm64<<<(B_*T_*HG_)/4, 128>>>(gk, kn);

    // tensor-core causal attention -> g_yh/g_yl (bf16 planes)
    attn_mma<<<512, 128, ATT_SMEM>>>();

    // output projection -> d_out
    gemm_mma<<<dim3(D_/128, MT_/128), 512, GEMM_SMEM>>>(yh, yl, woh, wol, out, MT_, D_, D_);

    // GDN scan accumulates into d_out
    gdn_kernel<<<128, 128>>>(gv, alpha, beta, out);
}